// round 13
// baseline (speedup 1.0000x reference)
#include <cuda_runtime.h>
#include <cuda_bf16.h>
#include <cuda_fp16.h>
#include <cstdint>
#include <math.h>

#define LSn 2
#define BSn 64
#define Tn 64
#define NHn 128
#define HW (4096*128)
#define OUT_FO   0
#define OUT_FCOV 64
#define OUT_X    4160
#define OUT_COV  2101312
#define OUT_LL   4198464

// ---------------- device scratch ----------------
__device__ __align__(256) __half g_h0i[HW];
__device__ __align__(256) __half g_h1i[HW];
__device__ __align__(256) __half g_Whh[2][512*128];
__device__ __align__(256) __half g_Wih[512*128];
__device__ __align__(256) __nv_bfloat16 g_Wi0hi[512*128];
__device__ __align__(256) __nv_bfloat16 g_Wi0lo[512*128];
__device__ __align__(256) __nv_bfloat16 g_xhi[4096*128];
__device__ __align__(256) __nv_bfloat16 g_xlo[4096*128];
__device__ float g_c0[2][HW];
__device__ float g_hT[2][HW];
__device__ float g_cT[2][HW];
__device__ __align__(256) float g_xproj[Tn*64*128*4];
__device__ __align__(16) float g_bsum2[512];
__device__ __align__(16) float g_bsum0v[512];

__device__ float g_up[2*64*128*128];
__device__ float g_Am[2*64*128*128];
__device__ float g_HA[64*128];
__device__ float g_innov[64*128];
__device__ float g_P[64*64];
__device__ float g_Pinv[64*64];
__device__ float g_T2[64*128];
__device__ float g_T1[128*128];
__device__ float g_AY[64*128];
__device__ float g_fout[64];
__device__ float g_fcov[64*64];

__device__ __forceinline__ float tanha(float x){
  float r; asm("tanh.approx.f32 %0, %1;" : "=f"(r) : "f"(x)); return r;
}
__device__ __forceinline__ float sigm(float x){ return fmaf(0.5f, tanha(0.5f*x), 0.5f); }
__device__ __forceinline__ uint32_t s2u(const void* p){
  uint32_t a;
  asm("{ .reg .u64 t; cvta.to.shared.u64 t, %1; cvt.u32.u64 %0, t; }" : "=r"(a) : "l"(p));
  return a;
}

#define SROW 272
#define TROW 80

#define MMA_BF16(d, a, b0_, b1_) \
  asm volatile("mma.sync.aligned.m16n8k16.row.col.f32.bf16.bf16.f32 " \
    "{%0,%1,%2,%3},{%4,%5,%6,%7},{%8,%9},{%0,%1,%2,%3};" \
    : "+f"((d)[0]),"+f"((d)[1]),"+f"((d)[2]),"+f"((d)[3]) \
    : "r"((a)[0]),"r"((a)[1]),"r"((a)[2]),"r"((a)[3]),"r"(b0_),"r"(b1_))

#define MMA_F16(d, a, b0_, b1_) \
  asm volatile("mma.sync.aligned.m16n8k16.row.col.f32.f16.f16.f32 " \
    "{%0,%1,%2,%3},{%4,%5,%6,%7},{%8,%9},{%0,%1,%2,%3};" \
    : "+f"((d)[0]),"+f"((d)[1]),"+f"((d)[2]),"+f"((d)[3]) \
    : "r"((a)[0]),"r"((a)[1]),"r"((a)[2]),"r"((a)[3]),"r"(b0_),"r"(b1_))

#define LDSM4(r, a) \
  asm volatile("ldmatrix.sync.aligned.m8n8.x4.shared.b16 {%0,%1,%2,%3}, [%4];" \
    : "=r"((r)[0]),"=r"((r)[1]),"=r"((r)[2]),"=r"((r)[3]) : "r"(a))

#define CLUSTER_BAR() do{ \
  asm volatile("barrier.cluster.arrive.aligned;" ::: "memory"); \
  asm volatile("barrier.cluster.wait.aligned;" ::: "memory"); }while(0)

#define CPA16(dst, src) \
  asm volatile("cp.async.ca.shared.global [%0], [%1], 16;" :: "r"(dst), "l"(src))
#define CPA_COMMIT() asm volatile("cp.async.commit_group;" ::: "memory")
#define CPA_WAIT0()  asm volatile("cp.async.wait_group 0;" ::: "memory")

#define STC16(addr, v) \
  asm volatile("st.shared::cluster.v4.b32 [%0], {%1,%2,%3,%4};" \
    :: "r"(addr), "r"((v).x), "r"((v).y), "r"((v).z), "r"((v).w) : "memory")

__device__ __forceinline__ void cp_tile(const __nv_bfloat16* __restrict__ src, char* dst, int tid){
  const uint4* s4 = (const uint4*)src;
  #pragma unroll
  for (int it=0; it<8; it++){
    int i = it*256 + tid;
    uint4 v = __ldcg(&s4[i]);
    int row = i>>4, ck = i&15;
    *(uint4*)(dst + row*SROW + ck*16) = v;
  }
}

__device__ __forceinline__ void cp_tile_a(const void* __restrict__ src, uint32_t dst, int tid){
  const uint4* s4 = (const uint4*)src;
  #pragma unroll
  for (int it=0; it<8; it++){
    int i = it*256 + tid;
    int row = i>>4, ck = i&15;
    CPA16(dst + row*SROW + ck*16, &s4[i]);
  }
}

// 3-term bf16-split GEMM (xproj only)
__device__ __forceinline__ void gemm_phase(float acc[8][2][4],
                                           uint32_t aH, uint32_t aL,
                                           uint32_t bH, uint32_t bL,
                                           const uint32_t* bRel){
  #pragma unroll
  for (int kc=0; kc<8; kc++){
    uint32_t ka = kc*32;
    uint32_t ah0[4], ah1[4], al0[4], al1[4];
    LDSM4(ah0, aH + ka);
    LDSM4(ah1, aH + 16*SROW + ka);
    LDSM4(al0, aL + ka);
    LDSM4(al1, aL + 16*SROW + ka);
    #pragma unroll
    for (int jp2=0; jp2<2; jp2++){
      uint32_t bh0[4], bh1[4], bl0[4], bl1[4];
      LDSM4(bh0, bH + bRel[jp2*2]   + ka);
      LDSM4(bh1, bH + bRel[jp2*2+1] + ka);
      LDSM4(bl0, bL + bRel[jp2*2]   + ka);
      LDSM4(bl1, bL + bRel[jp2*2+1] + ka);
      int p0 = jp2*4, p1 = p0+1, p2 = p0+2, p3 = p0+3;
      MMA_BF16(acc[p0][0], ah0, bh0[0], bh0[1]);
      MMA_BF16(acc[p0][1], ah1, bh0[0], bh0[1]);
      MMA_BF16(acc[p1][0], ah0, bh0[2], bh0[3]);
      MMA_BF16(acc[p1][1], ah1, bh0[2], bh0[3]);
      MMA_BF16(acc[p2][0], ah0, bh1[0], bh1[1]);
      MMA_BF16(acc[p2][1], ah1, bh1[0], bh1[1]);
      MMA_BF16(acc[p3][0], ah0, bh1[2], bh1[3]);
      MMA_BF16(acc[p3][1], ah1, bh1[2], bh1[3]);
      MMA_BF16(acc[p0][0], ah0, bl0[0], bl0[1]);
      MMA_BF16(acc[p0][1], ah1, bl0[0], bl0[1]);
      MMA_BF16(acc[p1][0], ah0, bl0[2], bl0[3]);
      MMA_BF16(acc[p1][1], ah1, bl0[2], bl0[3]);
      MMA_BF16(acc[p2][0], ah0, bl1[0], bl1[1]);
      MMA_BF16(acc[p2][1], ah1, bl1[0], bl1[1]);
      MMA_BF16(acc[p3][0], ah0, bl1[2], bl1[3]);
      MMA_BF16(acc[p3][1], ah1, bl1[2], bl1[3]);
      MMA_BF16(acc[p0][0], al0, bh0[0], bh0[1]);
      MMA_BF16(acc[p0][1], al1, bh0[0], bh0[1]);
      MMA_BF16(acc[p1][0], al0, bh0[2], bh0[3]);
      MMA_BF16(acc[p1][1], al1, bh0[2], bh0[3]);
      MMA_BF16(acc[p2][0], al0, bh1[0], bh1[1]);
      MMA_BF16(acc[p2][1], al1, bh1[0], bh1[1]);
      MMA_BF16(acc[p3][0], al0, bh1[2], bh1[3]);
      MMA_BF16(acc[p3][1], al1, bh1[2], bh1[3]);
    }
  }
}

// 1-term fp16 GEMM
__device__ __forceinline__ void gemm_phase1(float acc[8][2][4],
                                            uint32_t aF, uint32_t bF,
                                            const uint32_t* bRel){
  #pragma unroll
  for (int kc=0; kc<8; kc++){
    uint32_t ka = kc*32;
    uint32_t a0[4], a1[4];
    LDSM4(a0, aF + ka);
    LDSM4(a1, aF + 16*SROW + ka);
    #pragma unroll
    for (int jp2=0; jp2<2; jp2++){
      uint32_t b0[4], b1[4];
      LDSM4(b0, bF + bRel[jp2*2]   + ka);
      LDSM4(b1, bF + bRel[jp2*2+1] + ka);
      int p0 = jp2*4, p1 = p0+1, p2 = p0+2, p3 = p0+3;
      MMA_F16(acc[p0][0], a0, b0[0], b0[1]);
      MMA_F16(acc[p0][1], a1, b0[0], b0[1]);
      MMA_F16(acc[p1][0], a0, b0[2], b0[3]);
      MMA_F16(acc[p1][1], a1, b0[2], b0[3]);
      MMA_F16(acc[p2][0], a0, b1[0], b1[1]);
      MMA_F16(acc[p2][1], a1, b1[0], b1[1]);
      MMA_F16(acc[p3][0], a0, b1[2], b1[3]);
      MMA_F16(acc[p3][1], a1, b1[2], b1[3]);
    }
  }
}

#define MMA_GEO() \
  int tid = threadIdx.x, wid = tid>>5, lane = tid&31; \
  int g = lane>>2; \
  int wm = wid&3, wn = wid>>2; \
  int s = (lane&3)&1, csel = (lane&3)>>1; \
  int src_if = (g<<2) + (csel<<1); \
  int src_go = src_if + 1; (void)src_if; (void)src_go;

#define LDSM_GEO() \
  int aq = lane>>3, ar = lane&7; \
  uint32_t aRel = (uint32_t)(wm*32 + (aq&1)*8 + ar)*SROW + (uint32_t)(aq>>1)*16; \
  uint32_t bRel[4]; \
  { int bq = lane>>3, br = lane&7; \
    _Pragma("unroll") \
    for (int jp=0; jp<4; jp++) \
      bRel[jp] = (uint32_t)(wn*64 + (jp*2 + (bq>>1))*8 + br)*SROW + (uint32_t)(bq&1)*16; }

#define SHFL_GATES(A4) \
  float v0 = __shfl_sync(0xFFFFFFFFu, A4[0], src_if); \
  float v2 = __shfl_sync(0xFFFFFFFFu, A4[2], src_if); \
  float v1 = __shfl_sync(0xFFFFFFFFu, A4[1], src_if); \
  float v3 = __shfl_sync(0xFFFFFFFFu, A4[3], src_if); \
  float w0 = __shfl_sync(0xFFFFFFFFu, A4[0], src_go); \
  float w2 = __shfl_sync(0xFFFFFFFFu, A4[2], src_go); \
  float w1 = __shfl_sync(0xFFFFFFFFu, A4[1], src_go); \
  float w3 = __shfl_sync(0xFFFFFFFFu, A4[3], src_go); \
  float gi  = s ? v2 : v0; \
  float gf  = s ? v3 : v1; \
  float gg  = s ? w2 : w0; \
  float go_ = s ? w3 : w1;

// ---------------- prep ----------------
// coalesced transpose init: one block per (l,b)
__global__ __launch_bounds__(256) void k_init(const float* __restrict__ uhi){
  extern __shared__ __align__(16) float U[];   // [128][129]
  int lb = blockIdx.x, l = lb>>6, b = lb&63;
  int tid = threadIdx.x;
  const float* src = uhi + (long)lb*16384;     // [k][N]
  for (int i=tid;i<16384;i+=256) U[(i>>7)*129 + (i&127)] = src[i];
  __syncthreads();
  for (int i=tid;i<8192;i+=256){
    int j = i>>7, k = i&127;
    int row = (j*64+b)*128 + k;
    __half hv = __float2half_rn(U[k*129 + j]);
    if (l==0) g_h0i[row] = hv; else g_h1i[row] = hv;
    g_c0[l][row] = U[k*129 + j + 64];
  }
}

__global__ void k_prep(const float* __restrict__ W_ih, const float* __restrict__ W_hh,
                       const float* __restrict__ x,
                       const float* __restrict__ bih, const float* __restrict__ bhh){
  int idx = blockIdx.x*blockDim.x + threadIdx.x;
  if (idx < 131072){
    int k = idx & 127, cg = (idx>>7)&511, l = idx>>16;
    int ct = cg>>7, c = cg&127;
    int nat = (c&3)*128 + ct*32 + (c>>2);
    g_Whh[l][cg*128+k] = __float2half_rn(W_hh[l*65536 + nat*128 + k]);
    if (l==1)
      g_Wih[cg*128+k] = __float2half_rn(W_ih[65536 + nat*128 + k]);
  } else if (idx < 196608){
    int i2 = idx - 131072;
    int k = i2 & 127, cg = i2>>7;
    int ct = cg>>7, c = cg&127;
    int nat = (c&3)*128 + ct*32 + (c>>2);
    float wi = W_ih[nat*128 + k];
    __nv_bfloat16 ihi = __float2bfloat16(wi);
    g_Wi0hi[cg*128+k] = ihi;
    g_Wi0lo[cg*128+k] = __float2bfloat16(wi - __bfloat162float(ihi));
  } else if (idx < 720896){
    int i2 = idx - 196608;
    int d = i2 & 127, row = i2 >> 7;
    int b = row & 63, t = row >> 6;
    float v = x[(b*Tn + t)*128 + d];
    __nv_bfloat16 hi = __float2bfloat16(v);
    g_xhi[row*128+d] = hi;
    g_xlo[row*128+d] = __float2bfloat16(v - __bfloat162float(hi));
  } else {
    int i2 = idx - 720896;
    if (i2 < 1024){
      int ll = i2>>9, c = i2&511;
      float v = bih[i2] + bhh[i2];
      if (ll==1) g_bsum2[(c&127)*4 + (c>>7)] = v;
      else       g_bsum0v[(c&127)*4 + (c>>7)] = v;
    }
  }
}

#define SM_A0A 0
#define SM_A0B 34816
#define SM_A1  69632
#define SM_W0  104448
#define SM_W1  139264
#define SM_W2  174080
#define SM_ST  208896
#define SMEM_SZ  229376
#define SMEM_SZX 139264

// ---------------- HMMA xproj (bf16, 3-term, exact) ----------------
__global__ __launch_bounds__(256,1) void k_xprojM(){
  extern __shared__ __align__(16) char smem[];
  char* sAh = smem + SM_A0A;  char* sAl = smem + SM_A0B;
  char* sW0 = smem + SM_A1;   char* sW1 = smem + SM_W0;
  MMA_GEO();
  LDSM_GEO();
  uint32_t sb = s2u(smem);
  int rt = blockIdx.x>>2, ct = blockIdx.x&3;
  int rowbase = rt*128 + wm*32 + g + 8*s;
  int nbase   = ct*32 + wn*16 + csel;
  float4 bias4[8];
  #pragma unroll
  for (int in=0; in<8; in++) bias4[in] = ((const float4*)g_bsum0v)[nbase + in*2];

  cp_tile(&g_xhi[rt*16384], sAh, tid);
  cp_tile(&g_xlo[rt*16384], sAl, tid);
  cp_tile(&g_Wi0hi[ct*16384], sW0, tid);
  cp_tile(&g_Wi0lo[ct*16384], sW1, tid);
  __syncthreads();
  float acc[8][2][4];
  #pragma unroll
  for (int in=0;in<8;in++)
    #pragma unroll
    for (int im=0;im<2;im++)
      #pragma unroll
      for (int r=0;r<4;r++) acc[in][im][r] = 0.f;
  gemm_phase(acc, sb+SM_A0A+aRel, sb+SM_A0B+aRel, sb+SM_A1, sb+SM_W0, bRel);

  float4* dst = (float4*)g_xproj;
  #pragma unroll
  for (int im=0; im<2; im++){
    int row = rowbase + im*16;
    #pragma unroll
    for (int in=0; in<8; in++){
      float* A4 = acc[in][im];
      SHFL_GATES(A4);
      int n = nbase + in*2;
      float4 v;
      v.x = gi + bias4[in].x; v.y = gf + bias4[in].y;
      v.z = gg + bias4[in].z; v.w = go_ + bias4[in].w;
      __stcg(&dst[(long)row*128 + n], v);
    }
  }
}

// ---------------- persistent wavefront 2-layer fp16 LSTM (DSMEM, A0 double-buffered) ----------------
__global__ __launch_bounds__(256,1) __cluster_dims__(4,1,1) void k_lstm(){
  extern __shared__ __align__(16) char smem[];
  char* stage0 = smem + SM_ST;
  char* stage1 = smem + SM_ST + 10240;
  MMA_GEO();
  LDSM_GEO();
  uint32_t sb = s2u(smem);
  uint32_t a1F = sb + SM_A1 + aRel;
  int rt = blockIdx.x>>2, ct = blockIdx.x&3;
  int rowbase = rt*128 + wm*32 + g + 8*s;
  int nbase   = ct*32 + wn*16 + csel;
  float c0r[16], c1r[16];
  float4 bias4[8];

  uint32_t pA0[2][4], pA1[4];
  #pragma unroll
  for (int p=0;p<4;p++){
    asm("mapa.shared::cluster.u32 %0, %1, %2;" : "=r"(pA0[0][p]) : "r"(sb+SM_A0A), "r"(p));
    asm("mapa.shared::cluster.u32 %0, %1, %2;" : "=r"(pA0[1][p]) : "r"(sb+SM_A0B), "r"(p));
    asm("mapa.shared::cluster.u32 %0, %1, %2;" : "=r"(pA1[p])    : "r"(sb+SM_A1),  "r"(p));
  }

  cp_tile_a(&g_h0i[rt*16384], sb+SM_A0A, tid);
  cp_tile_a(&g_h1i[rt*16384], sb+SM_A1, tid);
  cp_tile_a(&g_Whh[0][ct*16384], sb+SM_W0, tid);
  cp_tile_a(&g_Whh[1][ct*16384], sb+SM_W1, tid);
  cp_tile_a(&g_Wih[ct*16384],    sb+SM_W2, tid);
  #pragma unroll
  for (int in=0; in<8; in++) bias4[in] = ((const float4*)g_bsum2)[nbase + in*2];
  #pragma unroll
  for (int im=0; im<2; im++)
    #pragma unroll
    for (int in=0; in<8; in++){
      c0r[im*8+in] = g_c0[0][(long)(rowbase+im*16)*128 + nbase + in*2];
      c1r[im*8+in] = g_c0[1][(long)(rowbase+im*16)*128 + nbase + in*2];
    }
  CPA_COMMIT(); CPA_WAIT0();
  CLUSTER_BAR();

  for (int r=0; r<65; r++){
    int p = r & 1;
    uint32_t a0cur = (p ? (uint32_t)SM_A0B : (uint32_t)SM_A0A);
    uint32_t a0F = sb + a0cur + aRel;
    float acc[8][2][4];
    if (r < 64){
      #pragma unroll
      for (int in=0;in<8;in++)
        #pragma unroll
        for (int im=0;im<2;im++)
          #pragma unroll
          for (int q=0;q<4;q++) acc[in][im][q] = 0.f;
      gemm_phase1(acc, a0F, sb+SM_W0, bRel);
      #pragma unroll
      for (int im=0; im<2; im++){
        int row = rowbase + im*16;
        int b = row & 63;
        const float4* xr = ((const float4*)g_xproj) + (((long)r*64+b)<<7);
        #pragma unroll
        for (int in=0; in<8; in++){
          float* A4 = acc[in][im];
          SHFL_GATES(A4);
          int n = nbase + in*2;
          float4 xg = xr[n];
          gi += xg.x; gf += xg.y; gg += xg.z; go_ += xg.w;
          int idx = im*8 + in;
          float cc = sigm(gf)*c0r[idx] + sigm(gi)*tanha(gg);
          c0r[idx] = cc;
          float hv = sigm(go_)*tanha(cc);
          int rl = row - rt*128;
          int nl = n - ct*32;
          *(__half*)(stage0 + rl*TROW + nl*2) = __float2half_rn(hv);
          if (r==63){
            long off = (long)row*128 + n;
            g_hT[0][off] = hv;
            g_cT[0][off] = cc;
          }
        }
      }
      __syncthreads();
      // scatter l0 h to ALL peers' other A0 buffer — races nothing, overlaps gemm l1
      #pragma unroll
      for (int it=0; it<2; it++){
        int i = it*256 + tid;
        int rowi = i>>2, seg = i&3;
        uint4 v = *(const uint4*)(stage0 + rowi*TROW + seg*16);
        uint32_t off = (uint32_t)rowi*SROW + (uint32_t)ct*64 + (uint32_t)seg*16;
        #pragma unroll
        for (int q=0;q<4;q++) STC16(pA0[p^1][q]+off, v);
      }
    }
    if (r > 0){
      #pragma unroll
      for (int in=0;in<8;in++)
        #pragma unroll
        for (int im=0;im<2;im++)
          #pragma unroll
          for (int q=0;q<4;q++) acc[in][im][q] = 0.f;
      gemm_phase1(acc, a0F, sb+SM_W2, bRel);
      gemm_phase1(acc, a1F, sb+SM_W1, bRel);
      #pragma unroll
      for (int im=0; im<2; im++){
        int row = rowbase + im*16;
        #pragma unroll
        for (int in=0; in<8; in++){
          float* A4 = acc[in][im];
          SHFL_GATES(A4);
          int n = nbase + in*2;
          gi += bias4[in].x; gf += bias4[in].y;
          gg += bias4[in].z; go_ += bias4[in].w;
          int idx = im*8 + in;
          float cc = sigm(gf)*c1r[idx] + sigm(gi)*tanha(gg);
          c1r[idx] = cc;
          float hv = sigm(go_)*tanha(cc);
          int rl = row - rt*128;
          int nl = n - ct*32;
          *(__half*)(stage1 + rl*TROW + nl*2) = __float2half_rn(hv);
          if (r==64){
            long off = (long)row*128 + n;
            g_hT[1][off] = hv;
            g_cT[1][off] = cc;
          }
        }
      }
    }
    CLUSTER_BAR();   // all l1 gemm reads of A1 complete cluster-wide; stage1 written
    if (r > 0 && r < 64){
      #pragma unroll
      for (int it=0; it<2; it++){
        int i = it*256 + tid;
        int rowi = i>>2, seg = i&3;
        uint4 v = *(const uint4*)(stage1 + rowi*TROW + seg*16);
        uint32_t off = (uint32_t)rowi*SROW + (uint32_t)ct*64 + (uint32_t)seg*16;
        #pragma unroll
        for (int q=0;q<4;q++) STC16(pA1[q]+off, v);
      }
    }
    CLUSTER_BAR();   // all scatters visible for next round
  }
}

// ---------------- EnKF tail ----------------
// coalesced transpose version: one block per (l,b)
__global__ __launch_bounds__(256) void k_up(const float* __restrict__ nh, const float* __restrict__ nc,
                                            const float* qp, const float* ep){
  extern __shared__ __align__(16) float V[];   // [128 n][129] + mu at end
  float* mu = V + 128*129;
  int lb = blockIdx.x, l = lb>>6, b = lb&63;
  int tid = threadIdx.x;
  float q = fabsf(*qp), e = fabsf(*ep);
  for (int i=tid; i<16384; i+=256){
    int N = i>>7, n = i&127;
    float v;
    if (N < 64)
      v = g_hT[l][(N*64+b)*128 + n] + q * nh[((N*LSn + l)*BSn + b)*128 + n];
    else {
      int j2 = N - 64;
      v = g_cT[l][(j2*64+b)*128 + n] + e * nc[((j2*LSn + l)*BSn + b)*128 + n];
    }
    V[n*129 + N] = v;
  }
  __syncthreads();
  if (tid < 128){
    float sm = 0.f;
    #pragma unroll 4
    for (int N=0;N<128;N++) sm += V[tid*129 + N];
    mu[tid] = sm*(1.f/128.f);
  }
  __syncthreads();
  long base = (long)lb*16384;
  for (int i=tid; i<16384; i+=256){
    int n = i>>7, N = i&127;
    float v = V[n*129 + N];
    g_up[(base + n*128)*0 + ((long)(lb*128+n))*128 + N] = v;
    g_Am[((long)(lb*128+n))*128 + N] = v - mu[n];
  }
}

__global__ void k_hxi(const float* __restrict__ Hm, const float* __restrict__ y){
  int b = blockIdx.x, N = threadIdx.x;
  __shared__ float Hs[128];
  Hs[N] = Hm[N]; __syncthreads();
  float sm = 0.f;
  for (int n=0;n<128;n++) sm += g_up[((long)(b*128+n))*128 + N] * Hs[n];
  __shared__ float red[128];
  red[N] = sm; __syncthreads();
  for (int st=64;st>0;st>>=1){ if (N<st) red[N]+=red[N+st]; __syncthreads(); }
  float mean = red[0]*(1.f/128.f);
  g_HA[b*128+N] = sm - mean;
  g_innov[b*128+N] = y[b] - sm;
}

__global__ void k_P(const float* rp){
  int c = blockIdx.x, d = threadIdx.x;
  float sm = 0.f;
  for (int N=0;N<128;N++) sm += g_HA[c*128+N]*g_HA[d*128+N];
  float r = *rp;
  g_P[c*64+d] = sm*(1.f/127.f) + (c==d ? r*r : 0.f);
}

__global__ void k_inv(){
  __shared__ float M[64][128];
  __shared__ float fcol[64];
  __shared__ int spiv;
  int tid = threadIdx.x;
  for (int e=tid;e<8192;e+=128){
    int r = e>>7, c = e&127;
    M[r][c] = (c<64) ? g_P[r*64+c] : ((c-64)==r ? 1.f : 0.f);
  }
  __syncthreads();
  for (int k=0;k<64;k++){
    if (tid==0){
      int p = k; float best = fabsf(M[k][k]);
      for (int rr=k+1;rr<64;rr++){ float v=fabsf(M[rr][k]); if (v>best){best=v;p=rr;} }
      spiv = p;
    }
    __syncthreads();
    int p = spiv;
    if (p != k){ float tmp = M[k][tid]; M[k][tid] = M[p][tid]; M[p][tid] = tmp; }
    __syncthreads();
    float pv = M[k][k];
    __syncthreads();
    M[k][tid] = M[k][tid] / pv;
    __syncthreads();
    if (tid < 64) fcol[tid] = M[tid][k];
    __syncthreads();
    for (int e=tid;e<8192;e+=128){
      int r = e>>7, c = e&127;
      if (r != k) M[r][c] -= fcol[r]*M[k][c];
    }
    __syncthreads();
  }
  for (int e=tid;e<4096;e+=128){
    int r = e>>6, d = e&63;
    g_Pinv[r*64+d] = M[r][64+d];
  }
}

__global__ void k_T2(){
  int c = blockIdx.x, M = threadIdx.x;
  float sm = 0.f;
  for (int d=0;d<64;d++) sm += g_Pinv[c*64+d]*g_innov[d*128+M];
  g_T2[c*128+M] = sm;
}

__global__ void k_T1(){
  int N = blockIdx.x, M = threadIdx.x;
  __shared__ float HAc[64];
  if (M < 64) HAc[M] = g_HA[M*128 + N];
  __syncthreads();
  float sm = 0.f;
  for (int c=0;c<64;c++) sm += HAc[c]*g_T2[c*128+M];
  g_T1[N*128+M] = sm;
}

#define GEMM_CHUNK(AS,BS_,ACC,TX,TY)                                   \
  _Pragma("unroll 4")                                                  \
  for (int k2=0;k2<32;k2++){                                           \
    float a_[8], b_[8];                                                \
    *(float4*)&a_[0] = *(const float4*)&AS[k2][(TY)*8];                \
    *(float4*)&a_[4] = *(const float4*)&AS[k2][(TY)*8+4];              \
    *(float4*)&b_[0] = *(const float4*)&BS_[k2][(TX)*8];               \
    *(float4*)&b_[4] = *(const float4*)&BS_[k2][(TX)*8+4];             \
    _Pragma("unroll")                                                  \
    for (int ii=0;ii<8;ii++){                                          \
      _Pragma("unroll")                                                \
      for (int jj=0;jj<8;jj++) ACC[ii][jj] += a_[ii]*b_[jj];           \
    }                                                                  \
  }

__global__ __launch_bounds__(256) void k_upd(float* __restrict__ out){
  __shared__ __align__(16) float As[32][132];
  __shared__ __align__(16) float Bs[32][132];
  int lb = blockIdx.x;
  int tid = threadIdx.x, tx = tid & 15, ty = tid >> 4;
  const float* Ab = &g_Am[(long)lb*16384];
  float acc[8][8] = {};
  for (int kc=0; kc<128; kc+=32){
    for (int i=tid;i<4096;i+=256){
      int r = i>>5, kk = i&31;
      As[kk][r] = Ab[r*128 + kc + kk];
    }
    for (int i=tid;i<4096;i+=256){
      int c = i&127, kk = i>>7;
      Bs[kk][c] = g_T1[(kc+kk)*128 + c];
    }
    __syncthreads();
    GEMM_CHUNK(As,Bs,acc,tx,ty);
    __syncthreads();
  }
  #pragma unroll
  for (int r=0;r<8;r++){
    int n = ty*8 + r;
    #pragma unroll
    for (int u=0;u<8;u++){
      int Mc = tx*8 + u;
      long idx = (long)lb*16384 + n*128 + Mc;
      out[OUT_X + idx] = g_up[idx] + acc[r][u]*(1.f/127.f);
    }
  }
}

__global__ __launch_bounds__(256) void k_cov(float* __restrict__ out){
  extern __shared__ __align__(16) float Sf[];
  __shared__ float mu[128];
  __shared__ float part[256];
  int lb = blockIdx.x;
  int tid = threadIdx.x, tx = tid & 15, ty = tid >> 4;
  const float* Xb = out + OUT_X + (long)lb*16384;
  for (int i=tid; i<16384; i+=256){
    int n = i>>7, k = i&127;
    Sf[k*132 + n] = Xb[i];
  }
  __syncthreads();
  {
    int n = tid & 127, half = tid >> 7;
    float sm = 0.f;
    for (int k=half*64; k<half*64+64; k++) sm += Sf[k*132 + n];
    part[tid] = sm;
    __syncthreads();
    if (tid < 128) mu[tid] = (part[tid] + part[tid+128])*(1.f/128.f);
    __syncthreads();
  }
  for (int i=tid; i<16384; i+=256){
    int k = i>>7, n = i&127;
    Sf[k*132 + n] -= mu[n];
  }
  __syncthreads();
  float acc[8][8] = {};
  typedef float (*RowP)[132];
  for (int kc=0; kc<128; kc+=32){
    RowP As = (RowP)(&Sf[kc*132]);
    GEMM_CHUNK(As, As, acc, tx, ty);
  }
  #pragma unroll
  for (int r=0;r<8;r++){
    int n = ty*8 + r;
    #pragma unroll
    for (int u=0;u<8;u++){
      int m = tx*8 + u;
      out[OUT_COV + (long)lb*16384 + n*128 + m] = acc[r][u]*(1.f/127.f);
    }
  }
}

__global__ void k_Y(const float* __restrict__ Hm, float* __restrict__ out){
  int b = blockIdx.x, N = threadIdx.x;
  __shared__ float Hs[128];
  Hs[N] = Hm[N]; __syncthreads();
  float sm = 0.f;
  for (int n=0;n<128;n++) sm += out[OUT_X + (long)b*16384 + n*128 + N] * Hs[n];
  __shared__ float red[128];
  red[N] = sm; __syncthreads();
  for (int st=64;st>0;st>>=1){ if (N<st) red[N]+=red[N+st]; __syncthreads(); }
  float mean = red[0]*(1.f/128.f);
  g_AY[b*128+N] = sm - mean;
  if (N==0){ g_fout[b] = mean; out[OUT_FO + b] = mean; }
}

__global__ void k_fcov(const float* rp, float* __restrict__ out){
  int c = blockIdx.x, d = threadIdx.x;
  float sm = 0.f;
  for (int N=0;N<128;N++) sm += g_AY[c*128+N]*g_AY[d*128+N];
  float r = *rp;
  float v = sm*(1.f/127.f) + (c==d ? r*r : 0.f);
  g_fcov[c*64+d] = v;
  out[OUT_FCOV + c*64+d] = v;
}

__global__ void k_ll(const float* __restrict__ y, float* __restrict__ out){
  __shared__ float A[64][65];
  __shared__ float red[64];
  int tid = threadIdx.x;
  for (int c=0;c<64;c++) A[tid][c] = g_fcov[tid*64+c];
  __syncthreads();
  for (int k=0;k<64;k++){
    if (tid==k) A[k][k] = sqrtf(A[k][k]);
    __syncthreads();
    float lkk = A[k][k];
    if (tid>k) A[tid][k] /= lkk;
    __syncthreads();
    if (tid>k){
      float lrk = A[tid][k];
      for (int c=k+1;c<=tid;c++) A[tid][c] -= lrk*A[c][k];
    }
    __syncthreads();
  }
  red[tid] = 2.f*logf(A[tid][tid]);
  __syncthreads();
  for (int st=32;st>0;st>>=1){ if (tid<st) red[tid]+=red[tid+st]; __syncthreads(); }
  if (tid==0){
    float logdet = red[0];
    float z[64];
    for (int k=0;k<64;k++){
      float sm = y[k] - g_fout[k];
      for (int j=0;j<k;j++) sm -= A[k][j]*z[j];
      z[k] = sm / A[k][k];
    }
    float qs = 0.f;
    for (int k=0;k<64;k++) qs += z[k]*z[k];
    out[OUT_LL] = -0.5f*logdet - 0.5f*qs;
  }
}

extern "C" void kernel_launch(void* const* d_in, const int* in_sizes, int n_in,
                              void* d_out, int out_size){
  const float* x    = (const float*)d_in[0];
  const float* y    = (const float*)d_in[1];
  const float* uhi  = (const float*)d_in[2];
  const float* W_ih = (const float*)d_in[3];
  const float* W_hh = (const float*)d_in[4];
  const float* b_ih = (const float*)d_in[5];
  const float* b_hh = (const float*)d_in[6];
  const float* Hm   = (const float*)d_in[7];
  const float* q    = (const float*)d_in[8];
  const float* e    = (const float*)d_in[9];
  const float* r    = (const float*)d_in[10];
  const float* nh   = (const float*)d_in[11];
  const float* nc   = (const float*)d_in[12];
  float* out = (float*)d_out;

  static int smem_set = 0;
  if (!smem_set){
    cudaFuncSetAttribute(k_lstm,   cudaFuncAttributeMaxDynamicSharedMemorySize, SMEM_SZ);
    cudaFuncSetAttribute(k_xprojM, cudaFuncAttributeMaxDynamicSharedMemorySize, SMEM_SZX);
    cudaFuncSetAttribute(k_cov,    cudaFuncAttributeMaxDynamicSharedMemorySize, 128*132*4);
    cudaFuncSetAttribute(k_init,   cudaFuncAttributeMaxDynamicSharedMemorySize, 128*129*4);
    cudaFuncSetAttribute(k_up,     cudaFuncAttributeMaxDynamicSharedMemorySize, 128*129*4 + 512);
    smem_set = 1;
  }

  k_init<<<128, 256, 128*129*4>>>(uhi);                 // 0
  k_prep<<<2820, 256>>>(W_ih, W_hh, x, b_ih, b_hh);     // 1
  k_xprojM<<<128, 256, SMEM_SZX>>>();                   // 2
  k_lstm<<<128, 256, SMEM_SZ>>>();                      // 3 <- profiled

  k_up<<<128, 256, 128*129*4 + 512>>>(nh, nc, q, e);
  k_hxi<<<64, 128>>>(Hm, y);
  k_P<<<64, 64>>>(r);
  k_inv<<<1, 128>>>();
  k_T2<<<64, 128>>>();
  k_T1<<<128, 128>>>();
  k_upd<<<128, 256>>>(out);
  k_cov<<<128, 256, 128*132*4>>>(out);
  k_Y<<<64, 128>>>(Hm, out);
  k_fcov<<<64, 64>>>(r, out);
  k_ll<<<1, 64>>>(y, out);
}

// round 14
// speedup vs baseline: 1.1460x; 1.1460x over previous
#include <cuda_runtime.h>
#include <cuda_bf16.h>
#include <cuda_fp16.h>
#include <cstdint>
#include <math.h>

#define LSn 2
#define BSn 64
#define Tn 64
#define NHn 128
#define HW (4096*128)
#define OUT_FO   0
#define OUT_FCOV 64
#define OUT_X    4160
#define OUT_COV  2101312
#define OUT_LL   4198464

// ---------------- device scratch ----------------
__device__ __align__(256) __half g_h0i[HW];
__device__ __align__(256) __half g_h1i[HW];
__device__ __align__(256) __half g_Whh[2][512*128];
__device__ __align__(256) __half g_Wih[512*128];
__device__ __align__(256) __nv_bfloat16 g_Wi0hi[512*128];
__device__ __align__(256) __nv_bfloat16 g_Wi0lo[512*128];
__device__ __align__(256) __nv_bfloat16 g_xhi[4096*128];
__device__ __align__(256) __nv_bfloat16 g_xlo[4096*128];
__device__ float g_c0[2][HW];
__device__ float g_hT[2][HW];
__device__ float g_cT[2][HW];
__device__ __align__(256) float g_xproj[Tn*64*128*4];
__device__ __align__(16) float g_bsum2[512];
__device__ __align__(16) float g_bsum0v[512];

__device__ float g_up[2*64*128*128];
__device__ __align__(256) __nv_bfloat16 g_Amh[2*64*128*128];
__device__ __align__(256) __nv_bfloat16 g_Aml[2*64*128*128];
__device__ float g_HA[64*128];
__device__ float g_innov[64*128];
__device__ float g_P[64*64];
__device__ float g_Pinv[64*64];
__device__ float g_T2[64*128];
__device__ float g_T1[128*128];
__device__ __align__(256) __nv_bfloat16 g_T1th[128*128];   // transposed [M][N]
__device__ __align__(256) __nv_bfloat16 g_T1tl[128*128];
__device__ float g_AY[64*128];
__device__ float g_fout[64];
__device__ float g_fcov[64*64];

__device__ __forceinline__ float tanha(float x){
  float r; asm("tanh.approx.f32 %0, %1;" : "=f"(r) : "f"(x)); return r;
}
__device__ __forceinline__ float sigm(float x){ return fmaf(0.5f, tanha(0.5f*x), 0.5f); }
__device__ __forceinline__ uint32_t s2u(const void* p){
  uint32_t a;
  asm("{ .reg .u64 t; cvta.to.shared.u64 t, %1; cvt.u32.u64 %0, t; }" : "=r"(a) : "l"(p));
  return a;
}

#define SROW 272
#define TROW 80

#define MMA_BF16(d, a, b0_, b1_) \
  asm volatile("mma.sync.aligned.m16n8k16.row.col.f32.bf16.bf16.f32 " \
    "{%0,%1,%2,%3},{%4,%5,%6,%7},{%8,%9},{%0,%1,%2,%3};" \
    : "+f"((d)[0]),"+f"((d)[1]),"+f"((d)[2]),"+f"((d)[3]) \
    : "r"((a)[0]),"r"((a)[1]),"r"((a)[2]),"r"((a)[3]),"r"(b0_),"r"(b1_))

#define MMA_F16(d, a, b0_, b1_) \
  asm volatile("mma.sync.aligned.m16n8k16.row.col.f32.f16.f16.f32 " \
    "{%0,%1,%2,%3},{%4,%5,%6,%7},{%8,%9},{%0,%1,%2,%3};" \
    : "+f"((d)[0]),"+f"((d)[1]),"+f"((d)[2]),"+f"((d)[3]) \
    : "r"((a)[0]),"r"((a)[1]),"r"((a)[2]),"r"((a)[3]),"r"(b0_),"r"(b1_))

#define LDSM4(r, a) \
  asm volatile("ldmatrix.sync.aligned.m8n8.x4.shared.b16 {%0,%1,%2,%3}, [%4];" \
    : "=r"((r)[0]),"=r"((r)[1]),"=r"((r)[2]),"=r"((r)[3]) : "r"(a))

#define CLUSTER_BAR() do{ \
  asm volatile("barrier.cluster.arrive.aligned;" ::: "memory"); \
  asm volatile("barrier.cluster.wait.aligned;" ::: "memory"); }while(0)

#define CPA16(dst, src) \
  asm volatile("cp.async.ca.shared.global [%0], [%1], 16;" :: "r"(dst), "l"(src))
#define CPA_COMMIT() asm volatile("cp.async.commit_group;" ::: "memory")
#define CPA_WAIT0()  asm volatile("cp.async.wait_group 0;" ::: "memory")

#define STC16(addr, v) \
  asm volatile("st.shared::cluster.v4.b32 [%0], {%1,%2,%3,%4};" \
    :: "r"(addr), "r"((v).x), "r"((v).y), "r"((v).z), "r"((v).w) : "memory")

__device__ __forceinline__ void cp_tile(const __nv_bfloat16* __restrict__ src, char* dst, int tid){
  const uint4* s4 = (const uint4*)src;
  #pragma unroll
  for (int it=0; it<8; it++){
    int i = it*256 + tid;
    uint4 v = __ldcg(&s4[i]);
    int row = i>>4, ck = i&15;
    *(uint4*)(dst + row*SROW + ck*16) = v;
  }
}

__device__ __forceinline__ void cp_tile_a(const void* __restrict__ src, uint32_t dst, int tid){
  const uint4* s4 = (const uint4*)src;
  #pragma unroll
  for (int it=0; it<8; it++){
    int i = it*256 + tid;
    int row = i>>4, ck = i&15;
    CPA16(dst + row*SROW + ck*16, &s4[i]);
  }
}

// 3-term bf16-split GEMM
__device__ __forceinline__ void gemm_phase(float acc[8][2][4],
                                           uint32_t aH, uint32_t aL,
                                           uint32_t bH, uint32_t bL,
                                           const uint32_t* bRel){
  #pragma unroll
  for (int kc=0; kc<8; kc++){
    uint32_t ka = kc*32;
    uint32_t ah0[4], ah1[4], al0[4], al1[4];
    LDSM4(ah0, aH + ka);
    LDSM4(ah1, aH + 16*SROW + ka);
    LDSM4(al0, aL + ka);
    LDSM4(al1, aL + 16*SROW + ka);
    #pragma unroll
    for (int jp2=0; jp2<2; jp2++){
      uint32_t bh0[4], bh1[4], bl0[4], bl1[4];
      LDSM4(bh0, bH + bRel[jp2*2]   + ka);
      LDSM4(bh1, bH + bRel[jp2*2+1] + ka);
      LDSM4(bl0, bL + bRel[jp2*2]   + ka);
      LDSM4(bl1, bL + bRel[jp2*2+1] + ka);
      int p0 = jp2*4, p1 = p0+1, p2 = p0+2, p3 = p0+3;
      MMA_BF16(acc[p0][0], ah0, bh0[0], bh0[1]);
      MMA_BF16(acc[p0][1], ah1, bh0[0], bh0[1]);
      MMA_BF16(acc[p1][0], ah0, bh0[2], bh0[3]);
      MMA_BF16(acc[p1][1], ah1, bh0[2], bh0[3]);
      MMA_BF16(acc[p2][0], ah0, bh1[0], bh1[1]);
      MMA_BF16(acc[p2][1], ah1, bh1[0], bh1[1]);
      MMA_BF16(acc[p3][0], ah0, bh1[2], bh1[3]);
      MMA_BF16(acc[p3][1], ah1, bh1[2], bh1[3]);
      MMA_BF16(acc[p0][0], ah0, bl0[0], bl0[1]);
      MMA_BF16(acc[p0][1], ah1, bl0[0], bl0[1]);
      MMA_BF16(acc[p1][0], ah0, bl0[2], bl0[3]);
      MMA_BF16(acc[p1][1], ah1, bl0[2], bl0[3]);
      MMA_BF16(acc[p2][0], ah0, bl1[0], bl1[1]);
      MMA_BF16(acc[p2][1], ah1, bl1[0], bl1[1]);
      MMA_BF16(acc[p3][0], ah0, bl1[2], bl1[3]);
      MMA_BF16(acc[p3][1], ah1, bl1[2], bl1[3]);
      MMA_BF16(acc[p0][0], al0, bh0[0], bh0[1]);
      MMA_BF16(acc[p0][1], al1, bh0[0], bh0[1]);
      MMA_BF16(acc[p1][0], al0, bh0[2], bh0[3]);
      MMA_BF16(acc[p1][1], al1, bh0[2], bh0[3]);
      MMA_BF16(acc[p2][0], al0, bh1[0], bh1[1]);
      MMA_BF16(acc[p2][1], al1, bh1[0], bh1[1]);
      MMA_BF16(acc[p3][0], al0, bh1[2], bh1[3]);
      MMA_BF16(acc[p3][1], al1, bh1[2], bh1[3]);
    }
  }
}

// 1-term fp16 GEMM
__device__ __forceinline__ void gemm_phase1(float acc[8][2][4],
                                            uint32_t aF, uint32_t bF,
                                            const uint32_t* bRel){
  #pragma unroll
  for (int kc=0; kc<8; kc++){
    uint32_t ka = kc*32;
    uint32_t a0[4], a1[4];
    LDSM4(a0, aF + ka);
    LDSM4(a1, aF + 16*SROW + ka);
    #pragma unroll
    for (int jp2=0; jp2<2; jp2++){
      uint32_t b0[4], b1[4];
      LDSM4(b0, bF + bRel[jp2*2]   + ka);
      LDSM4(b1, bF + bRel[jp2*2+1] + ka);
      int p0 = jp2*4, p1 = p0+1, p2 = p0+2, p3 = p0+3;
      MMA_F16(acc[p0][0], a0, b0[0], b0[1]);
      MMA_F16(acc[p0][1], a1, b0[0], b0[1]);
      MMA_F16(acc[p1][0], a0, b0[2], b0[3]);
      MMA_F16(acc[p1][1], a1, b0[2], b0[3]);
      MMA_F16(acc[p2][0], a0, b1[0], b1[1]);
      MMA_F16(acc[p2][1], a1, b1[0], b1[1]);
      MMA_F16(acc[p3][0], a0, b1[2], b1[3]);
      MMA_F16(acc[p3][1], a1, b1[2], b1[3]);
    }
  }
}

#define MMA_GEO() \
  int tid = threadIdx.x, wid = tid>>5, lane = tid&31; \
  int g = lane>>2; \
  int wm = wid&3, wn = wid>>2; \
  int s = (lane&3)&1, csel = (lane&3)>>1; \
  int src_if = (g<<2) + (csel<<1); \
  int src_go = src_if + 1; (void)src_if; (void)src_go;

#define LDSM_GEO() \
  int aq = lane>>3, ar = lane&7; \
  uint32_t aRel = (uint32_t)(wm*32 + (aq&1)*8 + ar)*SROW + (uint32_t)(aq>>1)*16; \
  uint32_t bRel[4]; \
  { int bq = lane>>3, br = lane&7; \
    _Pragma("unroll") \
    for (int jp=0; jp<4; jp++) \
      bRel[jp] = (uint32_t)(wn*64 + (jp*2 + (bq>>1))*8 + br)*SROW + (uint32_t)(bq&1)*16; }

#define SHFL_GATES(A4) \
  float v0 = __shfl_sync(0xFFFFFFFFu, A4[0], src_if); \
  float v2 = __shfl_sync(0xFFFFFFFFu, A4[2], src_if); \
  float v1 = __shfl_sync(0xFFFFFFFFu, A4[1], src_if); \
  float v3 = __shfl_sync(0xFFFFFFFFu, A4[3], src_if); \
  float w0 = __shfl_sync(0xFFFFFFFFu, A4[0], src_go); \
  float w2 = __shfl_sync(0xFFFFFFFFu, A4[2], src_go); \
  float w1 = __shfl_sync(0xFFFFFFFFu, A4[1], src_go); \
  float w3 = __shfl_sync(0xFFFFFFFFu, A4[3], src_go); \
  float gi  = s ? v2 : v0; \
  float gf  = s ? v3 : v1; \
  float gg  = s ? w2 : w0; \
  float go_ = s ? w3 : w1;

// ---------------- prep ----------------
__global__ __launch_bounds__(256) void k_init(const float* __restrict__ uhi){
  extern __shared__ __align__(16) float U[];
  int lb = blockIdx.x, l = lb>>6, b = lb&63;
  int tid = threadIdx.x;
  const float* src = uhi + (long)lb*16384;
  for (int i=tid;i<16384;i+=256) U[(i>>7)*129 + (i&127)] = src[i];
  __syncthreads();
  for (int i=tid;i<8192;i+=256){
    int j = i>>7, k = i&127;
    int row = (j*64+b)*128 + k;
    __half hv = __float2half_rn(U[k*129 + j]);
    if (l==0) g_h0i[row] = hv; else g_h1i[row] = hv;
    g_c0[l][row] = U[k*129 + j + 64];
  }
}

__global__ void k_prep(const float* __restrict__ W_ih, const float* __restrict__ W_hh,
                       const float* __restrict__ x,
                       const float* __restrict__ bih, const float* __restrict__ bhh){
  int idx = blockIdx.x*blockDim.x + threadIdx.x;
  if (idx < 131072){
    int k = idx & 127, cg = (idx>>7)&511, l = idx>>16;
    int ct = cg>>7, c = cg&127;
    int nat = (c&3)*128 + ct*32 + (c>>2);
    g_Whh[l][cg*128+k] = __float2half_rn(W_hh[l*65536 + nat*128 + k]);
    if (l==1)
      g_Wih[cg*128+k] = __float2half_rn(W_ih[65536 + nat*128 + k]);
  } else if (idx < 196608){
    int i2 = idx - 131072;
    int k = i2 & 127, cg = i2>>7;
    int ct = cg>>7, c = cg&127;
    int nat = (c&3)*128 + ct*32 + (c>>2);
    float wi = W_ih[nat*128 + k];
    __nv_bfloat16 ihi = __float2bfloat16(wi);
    g_Wi0hi[cg*128+k] = ihi;
    g_Wi0lo[cg*128+k] = __float2bfloat16(wi - __bfloat162float(ihi));
  } else if (idx < 720896){
    int i2 = idx - 196608;
    int d = i2 & 127, row = i2 >> 7;
    int b = row & 63, t = row >> 6;
    float v = x[(b*Tn + t)*128 + d];
    __nv_bfloat16 hi = __float2bfloat16(v);
    g_xhi[row*128+d] = hi;
    g_xlo[row*128+d] = __float2bfloat16(v - __bfloat162float(hi));
  } else {
    int i2 = idx - 720896;
    if (i2 < 1024){
      int ll = i2>>9, c = i2&511;
      float v = bih[i2] + bhh[i2];
      if (ll==1) g_bsum2[(c&127)*4 + (c>>7)] = v;
      else       g_bsum0v[(c&127)*4 + (c>>7)] = v;
    }
  }
}

// xproj smem layout
#define X_AH 0
#define X_AL 34816
#define X_W0 69632
#define X_W1 104448
#define SMEM_X 139264
// lstm smem layout (round-12)
#define L_A0 0
#define L_A1 34816
#define L_W0 69632
#define L_W1 104448
#define L_W2 139264
#define L_ST 174080
#define SMEM_L 194560

// ---------------- HMMA xproj (bf16, 3-term, exact) ----------------
__global__ __launch_bounds__(256,1) void k_xprojM(){
  extern __shared__ __align__(16) char smem[];
  MMA_GEO();
  LDSM_GEO();
  uint32_t sb = s2u(smem);
  int rt = blockIdx.x>>2, ct = blockIdx.x&3;
  int rowbase = rt*128 + wm*32 + g + 8*s;
  int nbase   = ct*32 + wn*16 + csel;
  float4 bias4[8];
  #pragma unroll
  for (int in=0; in<8; in++) bias4[in] = ((const float4*)g_bsum0v)[nbase + in*2];

  cp_tile(&g_xhi[rt*16384], smem+X_AH, tid);
  cp_tile(&g_xlo[rt*16384], smem+X_AL, tid);
  cp_tile(&g_Wi0hi[ct*16384], smem+X_W0, tid);
  cp_tile(&g_Wi0lo[ct*16384], smem+X_W1, tid);
  __syncthreads();
  float acc[8][2][4];
  #pragma unroll
  for (int in=0;in<8;in++)
    #pragma unroll
    for (int im=0;im<2;im++)
      #pragma unroll
      for (int r=0;r<4;r++) acc[in][im][r] = 0.f;
  gemm_phase(acc, sb+X_AH+aRel, sb+X_AL+aRel, sb+X_W0, sb+X_W1, bRel);

  float4* dst = (float4*)g_xproj;
  #pragma unroll
  for (int im=0; im<2; im++){
    int row = rowbase + im*16;
    #pragma unroll
    for (int in=0; in<8; in++){
      float* A4 = acc[in][im];
      SHFL_GATES(A4);
      int n = nbase + in*2;
      float4 v;
      v.x = gi + bias4[in].x; v.y = gf + bias4[in].y;
      v.z = gg + bias4[in].z; v.w = go_ + bias4[in].w;
      __stcg(&dst[(long)row*128 + n], v);
    }
  }
}

// ---------------- persistent wavefront 2-layer fp16 LSTM (round-12 structure) ----------------
__global__ __launch_bounds__(256,1) __cluster_dims__(4,1,1) void k_lstm(){
  extern __shared__ __align__(16) char smem[];
  char* stage0 = smem + L_ST;
  char* stage1 = smem + L_ST + 10240;
  MMA_GEO();
  LDSM_GEO();
  uint32_t sb = s2u(smem);
  uint32_t a0F = sb + L_A0 + aRel, a1F = sb + L_A1 + aRel;
  int rt = blockIdx.x>>2, ct = blockIdx.x&3;
  int rowbase = rt*128 + wm*32 + g + 8*s;
  int nbase   = ct*32 + wn*16 + csel;
  float c0r[16], c1r[16];
  float4 bias4[8];

  uint32_t pA0[4], pA1[4];
  #pragma unroll
  for (int p=0;p<4;p++){
    asm("mapa.shared::cluster.u32 %0, %1, %2;" : "=r"(pA0[p]) : "r"(sb+L_A0), "r"(p));
    asm("mapa.shared::cluster.u32 %0, %1, %2;" : "=r"(pA1[p]) : "r"(sb+L_A1), "r"(p));
  }

  cp_tile_a(&g_h0i[rt*16384], sb+L_A0, tid);
  cp_tile_a(&g_h1i[rt*16384], sb+L_A1, tid);
  cp_tile_a(&g_Whh[0][ct*16384], sb+L_W0, tid);
  cp_tile_a(&g_Whh[1][ct*16384], sb+L_W1, tid);
  cp_tile_a(&g_Wih[ct*16384],    sb+L_W2, tid);
  #pragma unroll
  for (int in=0; in<8; in++) bias4[in] = ((const float4*)g_bsum2)[nbase + in*2];
  #pragma unroll
  for (int im=0; im<2; im++)
    #pragma unroll
    for (int in=0; in<8; in++){
      c0r[im*8+in] = g_c0[0][(long)(rowbase+im*16)*128 + nbase + in*2];
      c1r[im*8+in] = g_c0[1][(long)(rowbase+im*16)*128 + nbase + in*2];
    }
  CPA_COMMIT(); CPA_WAIT0();
  CLUSTER_BAR();

  for (int r=0; r<65; r++){
    float acc[8][2][4];
    if (r < 64){
      #pragma unroll
      for (int in=0;in<8;in++)
        #pragma unroll
        for (int im=0;im<2;im++)
          #pragma unroll
          for (int q=0;q<4;q++) acc[in][im][q] = 0.f;
      gemm_phase1(acc, a0F, sb+L_W0, bRel);
      #pragma unroll
      for (int im=0; im<2; im++){
        int row = rowbase + im*16;
        int b = row & 63;
        const float4* xr = ((const float4*)g_xproj) + (((long)r*64+b)<<7);
        #pragma unroll
        for (int in=0; in<8; in++){
          float* A4 = acc[in][im];
          SHFL_GATES(A4);
          int n = nbase + in*2;
          float4 xg = xr[n];
          gi += xg.x; gf += xg.y; gg += xg.z; go_ += xg.w;
          int idx = im*8 + in;
          float cc = sigm(gf)*c0r[idx] + sigm(gi)*tanha(gg);
          c0r[idx] = cc;
          float hv = sigm(go_)*tanha(cc);
          int rl = row - rt*128;
          int nl = n - ct*32;
          *(__half*)(stage0 + rl*TROW + nl*2) = __float2half_rn(hv);
          if (r==63){
            long off = (long)row*128 + n;
            g_hT[0][off] = hv;
            g_cT[0][off] = cc;
          }
        }
      }
    }
    if (r > 0){
      #pragma unroll
      for (int in=0;in<8;in++)
        #pragma unroll
        for (int im=0;im<2;im++)
          #pragma unroll
          for (int q=0;q<4;q++) acc[in][im][q] = 0.f;
      gemm_phase1(acc, a0F, sb+L_W2, bRel);
      gemm_phase1(acc, a1F, sb+L_W1, bRel);
      #pragma unroll
      for (int im=0; im<2; im++){
        int row = rowbase + im*16;
        #pragma unroll
        for (int in=0; in<8; in++){
          float* A4 = acc[in][im];
          SHFL_GATES(A4);
          int n = nbase + in*2;
          gi += bias4[in].x; gf += bias4[in].y;
          gg += bias4[in].z; go_ += bias4[in].w;
          int idx = im*8 + in;
          float cc = sigm(gf)*c1r[idx] + sigm(gi)*tanha(gg);
          c1r[idx] = cc;
          float hv = sigm(go_)*tanha(cc);
          int rl = row - rt*128;
          int nl = n - ct*32;
          *(__half*)(stage1 + rl*TROW + nl*2) = __float2half_rn(hv);
          if (r==64){
            long off = (long)row*128 + n;
            g_hT[1][off] = hv;
            g_cT[1][off] = cc;
          }
        }
      }
    }
    CLUSTER_BAR();
    if (r < 64){
      #pragma unroll
      for (int it=0; it<2; it++){
        int i = it*256 + tid;
        int rowi = i>>2, seg = i&3;
        uint4 v = *(const uint4*)(stage0 + rowi*TROW + seg*16);
        uint32_t off = (uint32_t)rowi*SROW + (uint32_t)ct*64 + (uint32_t)seg*16;
        #pragma unroll
        for (int q=0;q<4;q++) STC16(pA0[q]+off, v);
      }
    }
    if (r > 0 && r < 64){
      #pragma unroll
      for (int it=0; it<2; it++){
        int i = it*256 + tid;
        int rowi = i>>2, seg = i&3;
        uint4 v = *(const uint4*)(stage1 + rowi*TROW + seg*16);
        uint32_t off = (uint32_t)rowi*SROW + (uint32_t)ct*64 + (uint32_t)seg*16;
        #pragma unroll
        for (int q=0;q<4;q++) STC16(pA1[q]+off, v);
      }
    }
    CLUSTER_BAR();
  }
}

// ---------------- EnKF tail ----------------
// coalesced: one block per (l,b); also emits bf16 split of anomalies
__global__ __launch_bounds__(256) void k_up(const float* __restrict__ nh, const float* __restrict__ nc,
                                            const float* qp, const float* ep){
  extern __shared__ __align__(16) float V[];
  float* mu = V + 128*129;
  int lb = blockIdx.x, l = lb>>6, b = lb&63;
  int tid = threadIdx.x;
  float q = fabsf(*qp), e = fabsf(*ep);
  for (int i=tid; i<16384; i+=256){
    int N = i>>7, n = i&127;
    float v;
    if (N < 64)
      v = g_hT[l][(N*64+b)*128 + n] + q * nh[((N*LSn + l)*BSn + b)*128 + n];
    else {
      int j2 = N - 64;
      v = g_cT[l][(j2*64+b)*128 + n] + e * nc[((j2*LSn + l)*BSn + b)*128 + n];
    }
    V[n*129 + N] = v;
  }
  __syncthreads();
  if (tid < 128){
    float sm = 0.f;
    #pragma unroll 4
    for (int N=0;N<128;N++) sm += V[tid*129 + N];
    mu[tid] = sm*(1.f/128.f);
  }
  __syncthreads();
  for (int i=tid; i<16384; i+=256){
    int n = i>>7, N = i&127;
    float v = V[n*129 + N];
    long o = ((long)(lb*128+n))*128 + N;
    g_up[o] = v;
    float am = v - mu[n];
    __nv_bfloat16 h = __float2bfloat16(am);
    g_Amh[o] = h;
    g_Aml[o] = __float2bfloat16(am - __bfloat162float(h));
  }
}

__global__ void k_hxi(const float* __restrict__ Hm, const float* __restrict__ y){
  int b = blockIdx.x, N = threadIdx.x;
  __shared__ float Hs[128];
  Hs[N] = Hm[N]; __syncthreads();
  float sm = 0.f;
  for (int n=0;n<128;n++) sm += g_up[((long)(b*128+n))*128 + N] * Hs[n];
  __shared__ float red[128];
  red[N] = sm; __syncthreads();
  for (int st=64;st>0;st>>=1){ if (N<st) red[N]+=red[N+st]; __syncthreads(); }
  float mean = red[0]*(1.f/128.f);
  g_HA[b*128+N] = sm - mean;
  g_innov[b*128+N] = y[b] - sm;
}

__global__ void k_P(const float* rp){
  int c = blockIdx.x, d = threadIdx.x;
  float sm = 0.f;
  for (int N=0;N<128;N++) sm += g_HA[c*128+N]*g_HA[d*128+N];
  float r = *rp;
  g_P[c*64+d] = sm*(1.f/127.f) + (c==d ? r*r : 0.f);
}

// pivotless Gauss-Jordan on SPD P, 256 threads, 2 syncs/iter
__global__ __launch_bounds__(256) void k_inv(){
  __shared__ float M[64][129];
  __shared__ float fcol[64];
  int tid = threadIdx.x;
  for (int e=tid;e<8192;e+=256){
    int r = e>>7, c = e&127;
    M[r][c] = (c<64) ? g_P[r*64+c] : ((c-64)==r ? 1.f : 0.f);
  }
  __syncthreads();
  for (int k=0;k<64;k++){
    float rpv = 1.f / M[k][k];
    __syncthreads();
    if (tid < 128) M[k][tid] *= rpv;
    else if (tid < 192){
      int r = tid - 128;
      fcol[r] = (r==k) ? 0.f : M[r][k];
    }
    __syncthreads();
    for (int e=tid;e<8192;e+=256){
      int r = e>>7, c = e&127;
      M[r][c] = fmaf(-fcol[r], M[k][c], M[r][c]);
    }
    __syncthreads();
  }
  for (int e=tid;e<4096;e+=256){
    int r = e>>6, d = e&63;
    g_Pinv[r*64+d] = M[r][64+d];
  }
}

__global__ void k_T2(){
  int c = blockIdx.x, M = threadIdx.x;
  float sm = 0.f;
  for (int d=0;d<64;d++) sm += g_Pinv[c*64+d]*g_innov[d*128+M];
  g_T2[c*128+M] = sm;
}

__global__ void k_T1(){
  int N = blockIdx.x, M = threadIdx.x;
  __shared__ float HAc[64];
  if (M < 64) HAc[M] = g_HA[M*128 + N];
  __syncthreads();
  float sm = 0.f;
  for (int c=0;c<64;c++) sm += HAc[c]*g_T2[c*128+M];
  g_T1[N*128+M] = sm;
  // transposed bf16 split for HMMA k_upd: B[M][N]
  __nv_bfloat16 h = __float2bfloat16(sm);
  g_T1th[M*128+N] = h;
  g_T1tl[M*128+N] = __float2bfloat16(sm - __bfloat162float(h));
}

// ---------------- HMMA k_upd: X = up + Am @ T1 / 127 ----------------
__global__ __launch_bounds__(256,1) void k_upd(float* __restrict__ out){
  extern __shared__ __align__(16) char smem[];
  MMA_GEO();
  LDSM_GEO();
  (void)g; (void)csel; (void)s;
  uint32_t sb = s2u(smem);
  int lb = blockIdx.x;
  cp_tile(&g_Amh[(long)lb*16384], smem+X_AH, tid);
  cp_tile(&g_Aml[(long)lb*16384], smem+X_AL, tid);
  cp_tile(&g_T1th[0], smem+X_W0, tid);
  cp_tile(&g_T1tl[0], smem+X_W1, tid);
  __syncthreads();
  float acc[8][2][4];
  #pragma unroll
  for (int in=0;in<8;in++)
    #pragma unroll
    for (int im=0;im<2;im++)
      #pragma unroll
      for (int r=0;r<4;r++) acc[in][im][r] = 0.f;
  gemm_phase(acc, sb+X_AH+aRel, sb+X_AL+aRel, sb+X_W0, sb+X_W1, bRel);

  int r2 = lane>>2, cb2 = (lane&3)*2;
  #pragma unroll
  for (int im=0; im<2; im++){
    #pragma unroll
    for (int in=0; in<8; in++){
      float* A4 = acc[in][im];
      int row0 = wm*32 + im*16 + r2;
      int col  = wn*64 + in*8 + cb2;
      long i0 = (long)lb*16384 + (long)row0*128 + col;
      long i1 = i0 + 8*128;
      float2 u0 = *(const float2*)&g_up[i0];
      float2 u1 = *(const float2*)&g_up[i1];
      float2 o0, o1;
      o0.x = u0.x + A4[0]*(1.f/127.f); o0.y = u0.y + A4[1]*(1.f/127.f);
      o1.x = u1.x + A4[2]*(1.f/127.f); o1.y = u1.y + A4[3]*(1.f/127.f);
      *(float2*)&out[OUT_X + i0] = o0;
      *(float2*)&out[OUT_X + i1] = o1;
    }
  }
}

// ---------------- HMMA k_cov: Cov = An@An^T/127 ----------------
#define CV_SF 0
#define CV_T0 67584
#define CV_T1 102400
#define SMEM_CV 137216
__global__ __launch_bounds__(256,1) void k_cov(float* __restrict__ out){
  extern __shared__ __align__(16) char smem[];
  float* Sf = (float*)(smem + CV_SF);
  __shared__ float mu[128];
  __shared__ float part[256];
  MMA_GEO();
  LDSM_GEO();
  (void)g; (void)csel; (void)s;
  uint32_t sb = s2u(smem);
  int lb = blockIdx.x;
  const float* Xb = out + OUT_X + (long)lb*16384;
  for (int i=tid; i<16384; i+=256){
    int n = i>>7, k = i&127;
    Sf[k*132 + n] = Xb[i];
  }
  __syncthreads();
  {
    int n = tid & 127, half = tid >> 7;
    float sm = 0.f;
    for (int k=half*64; k<half*64+64; k++) sm += Sf[k*132 + n];
    part[tid] = sm;
    __syncthreads();
    if (tid < 128) mu[tid] = (part[tid] + part[tid+128])*(1.f/128.f);
    __syncthreads();
  }
  // write An bf16 hi/lo into padded tiles [n][k]
  for (int i=tid; i<16384; i+=256){
    int n = i>>7, k = i&127;
    float a = Sf[k*132 + n] - mu[n];
    __nv_bfloat16 h = __float2bfloat16(a);
    *(__nv_bfloat16*)(smem + CV_T0 + n*SROW + k*2) = h;
    *(__nv_bfloat16*)(smem + CV_T1 + n*SROW + k*2) = __float2bfloat16(a - __bfloat162float(h));
  }
  __syncthreads();
  float acc[8][2][4];
  #pragma unroll
  for (int in=0;in<8;in++)
    #pragma unroll
    for (int im=0;im<2;im++)
      #pragma unroll
      for (int r=0;r<4;r++) acc[in][im][r] = 0.f;
  gemm_phase(acc, sb+CV_T0+aRel, sb+CV_T1+aRel, sb+CV_T0, sb+CV_T1, bRel);

  int r2 = lane>>2, cb2 = (lane&3)*2;
  #pragma unroll
  for (int im=0; im<2; im++){
    #pragma unroll
    for (int in=0; in<8; in++){
      float* A4 = acc[in][im];
      int row0 = wm*32 + im*16 + r2;
      int col  = wn*64 + in*8 + cb2;
      long i0 = OUT_COV + (long)lb*16384 + (long)row0*128 + col;
      long i1 = i0 + 8*128;
      float2 o0, o1;
      o0.x = A4[0]*(1.f/127.f); o0.y = A4[1]*(1.f/127.f);
      o1.x = A4[2]*(1.f/127.f); o1.y = A4[3]*(1.f/127.f);
      *(float2*)&out[i0] = o0;
      *(float2*)&out[i1] = o1;
    }
  }
}

__global__ void k_Y(const float* __restrict__ Hm, float* __restrict__ out){
  int b = blockIdx.x, N = threadIdx.x;
  __shared__ float Hs[128];
  Hs[N] = Hm[N]; __syncthreads();
  float sm = 0.f;
  for (int n=0;n<128;n++) sm += out[OUT_X + (long)b*16384 + n*128 + N] * Hs[n];
  __shared__ float red[128];
  red[N] = sm; __syncthreads();
  for (int st=64;st>0;st>>=1){ if (N<st) red[N]+=red[N+st]; __syncthreads(); }
  float mean = red[0]*(1.f/128.f);
  g_AY[b*128+N] = sm - mean;
  if (N==0){ g_fout[b] = mean; out[OUT_FO + b] = mean; }
}

__global__ void k_fcov(const float* rp, float* __restrict__ out){
  int c = blockIdx.x, d = threadIdx.x;
  float sm = 0.f;
  for (int N=0;N<128;N++) sm += g_AY[c*128+N]*g_AY[d*128+N];
  float r = *rp;
  float v = sm*(1.f/127.f) + (c==d ? r*r : 0.f);
  g_fcov[c*64+d] = v;
  out[OUT_FCOV + c*64+d] = v;
}

__global__ void k_ll(const float* __restrict__ y, float* __restrict__ out){
  __shared__ float A[64][65];
  __shared__ float red[64];
  int tid = threadIdx.x;
  for (int c=0;c<64;c++) A[tid][c] = g_fcov[tid*64+c];
  __syncthreads();
  for (int k=0;k<64;k++){
    if (tid==k) A[k][k] = sqrtf(A[k][k]);
    __syncthreads();
    float lkk = A[k][k];
    if (tid>k) A[tid][k] /= lkk;
    __syncthreads();
    if (tid>k){
      float lrk = A[tid][k];
      for (int c=k+1;c<=tid;c++) A[tid][c] -= lrk*A[c][k];
    }
    __syncthreads();
  }
  red[tid] = 2.f*logf(A[tid][tid]);
  __syncthreads();
  for (int st=32;st>0;st>>=1){ if (tid<st) red[tid]+=red[tid+st]; __syncthreads(); }
  if (tid==0){
    float logdet = red[0];
    float z[64];
    for (int k=0;k<64;k++){
      float sm = y[k] - g_fout[k];
      for (int j=0;j<k;j++) sm -= A[k][j]*z[j];
      z[k] = sm / A[k][k];
    }
    float qs = 0.f;
    for (int k=0;k<64;k++) qs += z[k]*z[k];
    out[OUT_LL] = -0.5f*logdet - 0.5f*qs;
  }
}

extern "C" void kernel_launch(void* const* d_in, const int* in_sizes, int n_in,
                              void* d_out, int out_size){
  const float* x    = (const float*)d_in[0];
  const float* y    = (const float*)d_in[1];
  const float* uhi  = (const float*)d_in[2];
  const float* W_ih = (const float*)d_in[3];
  const float* W_hh = (const float*)d_in[4];
  const float* b_ih = (const float*)d_in[5];
  const float* b_hh = (const float*)d_in[6];
  const float* Hm   = (const float*)d_in[7];
  const float* q    = (const float*)d_in[8];
  const float* e    = (const float*)d_in[9];
  const float* r    = (const float*)d_in[10];
  const float* nh   = (const float*)d_in[11];
  const float* nc   = (const float*)d_in[12];
  float* out = (float*)d_out;

  static int smem_set = 0;
  if (!smem_set){
    cudaFuncSetAttribute(k_lstm,   cudaFuncAttributeMaxDynamicSharedMemorySize, SMEM_L);
    cudaFuncSetAttribute(k_xprojM, cudaFuncAttributeMaxDynamicSharedMemorySize, SMEM_X);
    cudaFuncSetAttribute(k_upd,    cudaFuncAttributeMaxDynamicSharedMemorySize, SMEM_X);
    cudaFuncSetAttribute(k_cov,    cudaFuncAttributeMaxDynamicSharedMemorySize, SMEM_CV);
    cudaFuncSetAttribute(k_init,   cudaFuncAttributeMaxDynamicSharedMemorySize, 128*129*4);
    cudaFuncSetAttribute(k_up,     cudaFuncAttributeMaxDynamicSharedMemorySize, 128*129*4 + 512);
    smem_set = 1;
  }

  k_init<<<128, 256, 128*129*4>>>(uhi);                 // 0
  k_prep<<<2820, 256>>>(W_ih, W_hh, x, b_ih, b_hh);     // 1
  k_xprojM<<<128, 256, SMEM_X>>>();                     // 2
  k_lstm<<<128, 256, SMEM_L>>>();                       // 3 <- profiled

  k_up<<<128, 256, 128*129*4 + 512>>>(nh, nc, q, e);
  k_hxi<<<64, 128>>>(Hm, y);
  k_P<<<64, 64>>>(r);
  k_inv<<<1, 256>>>();
  k_T2<<<64, 128>>>();
  k_T1<<<128, 128>>>();
  k_upd<<<128, 256, SMEM_X>>>(out);
  k_cov<<<128, 256, SMEM_CV>>>(out);
  k_Y<<<64, 128>>>(Hm, out);
  k_fcov<<<64, 64>>>(r, out);
  k_ll<<<1, 64>>>(y, out);
}

// round 15
// speedup vs baseline: 1.1644x; 1.0160x over previous
#include <cuda_runtime.h>
#include <cuda_bf16.h>
#include <cuda_fp16.h>
#include <cstdint>
#include <math.h>

#define LSn 2
#define BSn 64
#define Tn 64
#define NHn 128
#define HW (4096*128)
#define OUT_FO   0
#define OUT_FCOV 64
#define OUT_X    4160
#define OUT_COV  2101312
#define OUT_LL   4198464

// ---------------- device scratch ----------------
__device__ __align__(256) __half g_h0i[HW];
__device__ __align__(256) __half g_h1i[HW];
__device__ __align__(256) __half g_Whh[2][512*128];
__device__ __align__(256) __half g_Wih[512*128];
__device__ __align__(256) __nv_bfloat16 g_Wi0hi[512*128];
__device__ __align__(256) __nv_bfloat16 g_Wi0lo[512*128];
__device__ __align__(256) __nv_bfloat16 g_xhi[4096*128];
__device__ __align__(256) __nv_bfloat16 g_xlo[4096*128];
__device__ float g_c0[2][HW];
__device__ float g_hT[2][HW];
__device__ float g_cT[2][HW];
__device__ __align__(256) float g_xproj[Tn*64*128*4];
__device__ __align__(16) float g_bsum2[512];
__device__ __align__(16) float g_bsum0v[512];

__device__ float g_up[2*64*128*128];
__device__ __align__(256) __nv_bfloat16 g_Amh[2*64*128*128];
__device__ __align__(256) __nv_bfloat16 g_Aml[2*64*128*128];
__device__ float g_HA[64*128];
__device__ float g_innov[64*128];
__device__ float g_P[64*64];
__device__ float g_Pinv[64*64];
__device__ float g_T2[64*128];
__device__ float g_T1[128*128];
__device__ __align__(256) __nv_bfloat16 g_T1th[128*128];
__device__ __align__(256) __nv_bfloat16 g_T1tl[128*128];
__device__ float g_AY[64*128];
__device__ float g_fout[64];
__device__ float g_fcov[64*64];

__device__ __forceinline__ float tanha(float x){
  float r; asm("tanh.approx.f32 %0, %1;" : "=f"(r) : "f"(x)); return r;
}
__device__ __forceinline__ float sigm(float x){ return fmaf(0.5f, tanha(0.5f*x), 0.5f); }
__device__ __forceinline__ uint32_t s2u(const void* p){
  uint32_t a;
  asm("{ .reg .u64 t; cvta.to.shared.u64 t, %1; cvt.u32.u64 %0, t; }" : "=r"(a) : "l"(p));
  return a;
}

#define SROW 272
#define TROW 80

#define MMA_BF16(d, a, b0_, b1_) \
  asm volatile("mma.sync.aligned.m16n8k16.row.col.f32.bf16.bf16.f32 " \
    "{%0,%1,%2,%3},{%4,%5,%6,%7},{%8,%9},{%0,%1,%2,%3};" \
    : "+f"((d)[0]),"+f"((d)[1]),"+f"((d)[2]),"+f"((d)[3]) \
    : "r"((a)[0]),"r"((a)[1]),"r"((a)[2]),"r"((a)[3]),"r"(b0_),"r"(b1_))

#define MMA_F16(d, a, b0_, b1_) \
  asm volatile("mma.sync.aligned.m16n8k16.row.col.f32.f16.f16.f32 " \
    "{%0,%1,%2,%3},{%4,%5,%6,%7},{%8,%9},{%0,%1,%2,%3};" \
    : "+f"((d)[0]),"+f"((d)[1]),"+f"((d)[2]),"+f"((d)[3]) \
    : "r"((a)[0]),"r"((a)[1]),"r"((a)[2]),"r"((a)[3]),"r"(b0_),"r"(b1_))

#define LDSM4(r, a) \
  asm volatile("ldmatrix.sync.aligned.m8n8.x4.shared.b16 {%0,%1,%2,%3}, [%4];" \
    : "=r"((r)[0]),"=r"((r)[1]),"=r"((r)[2]),"=r"((r)[3]) : "r"(a))

#define CLUSTER_BAR() do{ \
  asm volatile("barrier.cluster.arrive.aligned;" ::: "memory"); \
  asm volatile("barrier.cluster.wait.aligned;" ::: "memory"); }while(0)

#define CPA16(dst, src) \
  asm volatile("cp.async.ca.shared.global [%0], [%1], 16;" :: "r"(dst), "l"(src))
#define CPA_COMMIT() asm volatile("cp.async.commit_group;" ::: "memory")
#define CPA_WAIT0()  asm volatile("cp.async.wait_group 0;" ::: "memory")

#define STC16(addr, v) \
  asm volatile("st.shared::cluster.v4.b32 [%0], {%1,%2,%3,%4};" \
    :: "r"(addr), "r"((v).x), "r"((v).y), "r"((v).z), "r"((v).w) : "memory")

__device__ __forceinline__ void cp_tile(const __nv_bfloat16* __restrict__ src, char* dst, int tid){
  const uint4* s4 = (const uint4*)src;
  #pragma unroll
  for (int it=0; it<8; it++){
    int i = it*256 + tid;
    uint4 v = __ldcg(&s4[i]);
    int row = i>>4, ck = i&15;
    *(uint4*)(dst + row*SROW + ck*16) = v;
  }
}

__device__ __forceinline__ void cp_tile_a512(const void* __restrict__ src, uint32_t dst, int tid){
  const uint4* s4 = (const uint4*)src;
  #pragma unroll
  for (int it=0; it<4; it++){
    int i = it*512 + tid;
    int row = i>>4, ck = i&15;
    CPA16(dst + row*SROW + ck*16, &s4[i]);
  }
}

// 3-term bf16-split GEMM (tail kernels, 256 threads)
__device__ __forceinline__ void gemm_phase(float acc[8][2][4],
                                           uint32_t aH, uint32_t aL,
                                           uint32_t bH, uint32_t bL,
                                           const uint32_t* bRel){
  #pragma unroll
  for (int kc=0; kc<8; kc++){
    uint32_t ka = kc*32;
    uint32_t ah0[4], ah1[4], al0[4], al1[4];
    LDSM4(ah0, aH + ka);
    LDSM4(ah1, aH + 16*SROW + ka);
    LDSM4(al0, aL + ka);
    LDSM4(al1, aL + 16*SROW + ka);
    #pragma unroll
    for (int jp2=0; jp2<2; jp2++){
      uint32_t bh0[4], bh1[4], bl0[4], bl1[4];
      LDSM4(bh0, bH + bRel[jp2*2]   + ka);
      LDSM4(bh1, bH + bRel[jp2*2+1] + ka);
      LDSM4(bl0, bL + bRel[jp2*2]   + ka);
      LDSM4(bl1, bL + bRel[jp2*2+1] + ka);
      int p0 = jp2*4, p1 = p0+1, p2 = p0+2, p3 = p0+3;
      MMA_BF16(acc[p0][0], ah0, bh0[0], bh0[1]);
      MMA_BF16(acc[p0][1], ah1, bh0[0], bh0[1]);
      MMA_BF16(acc[p1][0], ah0, bh0[2], bh0[3]);
      MMA_BF16(acc[p1][1], ah1, bh0[2], bh0[3]);
      MMA_BF16(acc[p2][0], ah0, bh1[0], bh1[1]);
      MMA_BF16(acc[p2][1], ah1, bh1[0], bh1[1]);
      MMA_BF16(acc[p3][0], ah0, bh1[2], bh1[3]);
      MMA_BF16(acc[p3][1], ah1, bh1[2], bh1[3]);
      MMA_BF16(acc[p0][0], ah0, bl0[0], bl0[1]);
      MMA_BF16(acc[p0][1], ah1, bl0[0], bl0[1]);
      MMA_BF16(acc[p1][0], ah0, bl0[2], bl0[3]);
      MMA_BF16(acc[p1][1], ah1, bl0[2], bl0[3]);
      MMA_BF16(acc[p2][0], ah0, bl1[0], bl1[1]);
      MMA_BF16(acc[p2][1], ah1, bl1[0], bl1[1]);
      MMA_BF16(acc[p3][0], ah0, bl1[2], bl1[3]);
      MMA_BF16(acc[p3][1], ah1, bl1[2], bl1[3]);
      MMA_BF16(acc[p0][0], al0, bh0[0], bh0[1]);
      MMA_BF16(acc[p0][1], al1, bh0[0], bh0[1]);
      MMA_BF16(acc[p1][0], al0, bh0[2], bh0[3]);
      MMA_BF16(acc[p1][1], al1, bh0[2], bh0[3]);
      MMA_BF16(acc[p2][0], al0, bh1[0], bh1[1]);
      MMA_BF16(acc[p2][1], al1, bh1[0], bh1[1]);
      MMA_BF16(acc[p3][0], al0, bh1[2], bh1[3]);
      MMA_BF16(acc[p3][1], al1, bh1[2], bh1[3]);
    }
  }
}

// 1-term fp16 GEMM, half-width warp tile (32x32), 16 warps
__device__ __forceinline__ void gemm_phase1h(float acc[4][2][4],
                                             uint32_t aF, uint32_t bF,
                                             const uint32_t* bRel){
  #pragma unroll
  for (int kc=0; kc<8; kc++){
    uint32_t ka = kc*32;
    uint32_t a0[4], a1[4], b0[4], b1[4];
    LDSM4(a0, aF + ka);
    LDSM4(a1, aF + 16*SROW + ka);
    LDSM4(b0, bF + bRel[0] + ka);
    LDSM4(b1, bF + bRel[1] + ka);
    MMA_F16(acc[0][0], a0, b0[0], b0[1]);
    MMA_F16(acc[0][1], a1, b0[0], b0[1]);
    MMA_F16(acc[1][0], a0, b0[2], b0[3]);
    MMA_F16(acc[1][1], a1, b0[2], b0[3]);
    MMA_F16(acc[2][0], a0, b1[0], b1[1]);
    MMA_F16(acc[2][1], a1, b1[0], b1[1]);
    MMA_F16(acc[3][0], a0, b1[2], b1[3]);
    MMA_F16(acc[3][1], a1, b1[2], b1[3]);
  }
}

#define MMA_GEO() \
  int tid = threadIdx.x, wid = tid>>5, lane = tid&31; \
  int g = lane>>2; \
  int wm = wid&3, wn = wid>>2; \
  int s = (lane&3)&1, csel = (lane&3)>>1; \
  int src_if = (g<<2) + (csel<<1); \
  int src_go = src_if + 1; (void)src_if; (void)src_go;

#define LDSM_GEO() \
  int aq = lane>>3, ar = lane&7; \
  uint32_t aRel = (uint32_t)(wm*32 + (aq&1)*8 + ar)*SROW + (uint32_t)(aq>>1)*16; \
  uint32_t bRel[4]; \
  { int bq = lane>>3, br = lane&7; \
    _Pragma("unroll") \
    for (int jp=0; jp<4; jp++) \
      bRel[jp] = (uint32_t)(wn*64 + (jp*2 + (bq>>1))*8 + br)*SROW + (uint32_t)(bq&1)*16; }

#define SHFL_GATES(A4) \
  float v0 = __shfl_sync(0xFFFFFFFFu, A4[0], src_if); \
  float v2 = __shfl_sync(0xFFFFFFFFu, A4[2], src_if); \
  float v1 = __shfl_sync(0xFFFFFFFFu, A4[1], src_if); \
  float v3 = __shfl_sync(0xFFFFFFFFu, A4[3], src_if); \
  float w0 = __shfl_sync(0xFFFFFFFFu, A4[0], src_go); \
  float w2 = __shfl_sync(0xFFFFFFFFu, A4[2], src_go); \
  float w1 = __shfl_sync(0xFFFFFFFFu, A4[1], src_go); \
  float w3 = __shfl_sync(0xFFFFFFFFu, A4[3], src_go); \
  float gi  = s ? v2 : v0; \
  float gf  = s ? v3 : v1; \
  float gg  = s ? w2 : w0; \
  float go_ = s ? w3 : w1;

// ---------------- prep ----------------
__global__ __launch_bounds__(256) void k_init(const float* __restrict__ uhi){
  extern __shared__ __align__(16) float U[];
  int lb = blockIdx.x, l = lb>>6, b = lb&63;
  int tid = threadIdx.x;
  const float* src = uhi + (long)lb*16384;
  for (int i=tid;i<16384;i+=256) U[(i>>7)*129 + (i&127)] = src[i];
  __syncthreads();
  for (int i=tid;i<8192;i+=256){
    int j = i>>7, k = i&127;
    int row = (j*64+b)*128 + k;
    __half hv = __float2half_rn(U[k*129 + j]);
    if (l==0) g_h0i[row] = hv; else g_h1i[row] = hv;
    g_c0[l][row] = U[k*129 + j + 64];
  }
}

__global__ void k_prep(const float* __restrict__ W_ih, const float* __restrict__ W_hh,
                       const float* __restrict__ x,
                       const float* __restrict__ bih, const float* __restrict__ bhh){
  int idx = blockIdx.x*blockDim.x + threadIdx.x;
  if (idx < 131072){
    int k = idx & 127, cg = (idx>>7)&511, l = idx>>16;
    int ct = cg>>7, c = cg&127;
    int nat = (c&3)*128 + ct*32 + (c>>2);
    g_Whh[l][cg*128+k] = __float2half_rn(W_hh[l*65536 + nat*128 + k]);
    if (l==1)
      g_Wih[cg*128+k] = __float2half_rn(W_ih[65536 + nat*128 + k]);
  } else if (idx < 196608){
    int i2 = idx - 131072;
    int k = i2 & 127, cg = i2>>7;
    int ct = cg>>7, c = cg&127;
    int nat = (c&3)*128 + ct*32 + (c>>2);
    float wi = W_ih[nat*128 + k];
    __nv_bfloat16 ihi = __float2bfloat16(wi);
    g_Wi0hi[cg*128+k] = ihi;
    g_Wi0lo[cg*128+k] = __float2bfloat16(wi - __bfloat162float(ihi));
  } else if (idx < 720896){
    int i2 = idx - 196608;
    int d = i2 & 127, row = i2 >> 7;
    int b = row & 63, t = row >> 6;
    float v = x[(b*Tn + t)*128 + d];
    __nv_bfloat16 hi = __float2bfloat16(v);
    g_xhi[row*128+d] = hi;
    g_xlo[row*128+d] = __float2bfloat16(v - __bfloat162float(hi));
  } else {
    int i2 = idx - 720896;
    if (i2 < 1024){
      int ll = i2>>9, c = i2&511;
      float v = bih[i2] + bhh[i2];
      if (ll==1) g_bsum2[(c&127)*4 + (c>>7)] = v;
      else       g_bsum0v[(c&127)*4 + (c>>7)] = v;
    }
  }
}

#define X_AH 0
#define X_AL 34816
#define X_W0 69632
#define X_W1 104448
#define SMEM_X 139264
#define L_A0 0
#define L_A1 34816
#define L_W0 69632
#define L_W1 104448
#define L_W2 139264
#define L_ST 174080
#define SMEM_L 194560

// ---------------- HMMA xproj (bf16, 3-term, exact) ----------------
__global__ __launch_bounds__(256,1) void k_xprojM(){
  extern __shared__ __align__(16) char smem[];
  MMA_GEO();
  LDSM_GEO();
  uint32_t sb = s2u(smem);
  int rt = blockIdx.x>>2, ct = blockIdx.x&3;
  int rowbase = rt*128 + wm*32 + g + 8*s;
  int nbase   = ct*32 + wn*16 + csel;
  float4 bias4[8];
  #pragma unroll
  for (int in=0; in<8; in++) bias4[in] = ((const float4*)g_bsum0v)[nbase + in*2];

  cp_tile(&g_xhi[rt*16384], smem+X_AH, tid);
  cp_tile(&g_xlo[rt*16384], smem+X_AL, tid);
  cp_tile(&g_Wi0hi[ct*16384], smem+X_W0, tid);
  cp_tile(&g_Wi0lo[ct*16384], smem+X_W1, tid);
  __syncthreads();
  float acc[8][2][4];
  #pragma unroll
  for (int in=0;in<8;in++)
    #pragma unroll
    for (int im=0;im<2;im++)
      #pragma unroll
      for (int r=0;r<4;r++) acc[in][im][r] = 0.f;
  gemm_phase(acc, sb+X_AH+aRel, sb+X_AL+aRel, sb+X_W0, sb+X_W1, bRel);

  float4* dst = (float4*)g_xproj;
  #pragma unroll
  for (int im=0; im<2; im++){
    int row = rowbase + im*16;
    #pragma unroll
    for (int in=0; in<8; in++){
      float* A4 = acc[in][im];
      SHFL_GATES(A4);
      int n = nbase + in*2;
      float4 v;
      v.x = gi + bias4[in].x; v.y = gf + bias4[in].y;
      v.z = gg + bias4[in].z; v.w = go_ + bias4[in].w;
      __stcg(&dst[(long)row*128 + n], v);
    }
  }
}

// ---------------- persistent wavefront 2-layer fp16 LSTM (512 threads, 16 warps) ----------------
__global__ __launch_bounds__(512,1) __cluster_dims__(4,1,1) void k_lstm(){
  extern __shared__ __align__(16) char smem[];
  char* stage0 = smem + L_ST;
  char* stage1 = smem + L_ST + 10240;
  int tid = threadIdx.x, wid = tid>>5, lane = tid&31;
  int g = lane>>2;
  int wm = wid&3, wn = wid>>2;                // 4x4 warp grid, tile 32x32
  int s = lane&1, csel = (lane&3)>>1;
  int src_if = (g<<2) + (csel<<1);
  int src_go = src_if + 1;
  int aq = lane>>3, ar = lane&7;
  uint32_t aRel = (uint32_t)(wm*32 + (aq&1)*8 + ar)*SROW + (uint32_t)(aq>>1)*16;
  uint32_t bRel[2];
  { int bq = lane>>3, br = lane&7;
    #pragma unroll
    for (int jp=0; jp<2; jp++)
      bRel[jp] = (uint32_t)(wn*32 + (jp*2 + (bq>>1))*8 + br)*SROW + (uint32_t)(bq&1)*16; }
  uint32_t sb = s2u(smem);
  uint32_t a0F = sb + L_A0 + aRel, a1F = sb + L_A1 + aRel;
  int rt = blockIdx.x>>2, ct = blockIdx.x&3;
  int rowbase = rt*128 + wm*32 + g + 8*s;
  int nbase   = ct*32 + wn*8 + csel;
  float c0r[8], c1r[8];
  float4 bias4[4];

  uint32_t pA0[4], pA1[4];
  #pragma unroll
  for (int p=0;p<4;p++){
    asm("mapa.shared::cluster.u32 %0, %1, %2;" : "=r"(pA0[p]) : "r"(sb+L_A0), "r"(p));
    asm("mapa.shared::cluster.u32 %0, %1, %2;" : "=r"(pA1[p]) : "r"(sb+L_A1), "r"(p));
  }

  cp_tile_a512(&g_h0i[rt*16384], sb+L_A0, tid);
  cp_tile_a512(&g_h1i[rt*16384], sb+L_A1, tid);
  cp_tile_a512(&g_Whh[0][ct*16384], sb+L_W0, tid);
  cp_tile_a512(&g_Whh[1][ct*16384], sb+L_W1, tid);
  cp_tile_a512(&g_Wih[ct*16384],    sb+L_W2, tid);
  #pragma unroll
  for (int in=0; in<4; in++) bias4[in] = ((const float4*)g_bsum2)[nbase + in*2];
  #pragma unroll
  for (int im=0; im<2; im++)
    #pragma unroll
    for (int in=0; in<4; in++){
      c0r[im*4+in] = g_c0[0][(long)(rowbase+im*16)*128 + nbase + in*2];
      c1r[im*4+in] = g_c0[1][(long)(rowbase+im*16)*128 + nbase + in*2];
    }
  CPA_COMMIT(); CPA_WAIT0();
  CLUSTER_BAR();

  for (int r=0; r<65; r++){
    float acc[4][2][4];
    if (r < 64){
      #pragma unroll
      for (int in=0;in<4;in++)
        #pragma unroll
        for (int im=0;im<2;im++)
          #pragma unroll
          for (int q=0;q<4;q++) acc[in][im][q] = 0.f;
      gemm_phase1h(acc, a0F, sb+L_W0, bRel);
      #pragma unroll
      for (int im=0; im<2; im++){
        int row = rowbase + im*16;
        int b = row & 63;
        const float4* xr = ((const float4*)g_xproj) + (((long)r*64+b)<<7);
        #pragma unroll
        for (int in=0; in<4; in++){
          float* A4 = acc[in][im];
          SHFL_GATES(A4);
          int n = nbase + in*2;
          float4 xg = xr[n];
          gi += xg.x; gf += xg.y; gg += xg.z; go_ += xg.w;
          int idx = im*4 + in;
          float cc = sigm(gf)*c0r[idx] + sigm(gi)*tanha(gg);
          c0r[idx] = cc;
          float hv = sigm(go_)*tanha(cc);
          int rl = row - rt*128;
          int nl = n - ct*32;
          *(__half*)(stage0 + rl*TROW + nl*2) = __float2half_rn(hv);
          if (r==63){
            long off = (long)row*128 + n;
            g_hT[0][off] = hv;
            g_cT[0][off] = cc;
          }
        }
      }
    }
    if (r > 0){
      #pragma unroll
      for (int in=0;in<4;in++)
        #pragma unroll
        for (int im=0;im<2;im++)
          #pragma unroll
          for (int q=0;q<4;q++) acc[in][im][q] = 0.f;
      gemm_phase1h(acc, a0F, sb+L_W2, bRel);
      gemm_phase1h(acc, a1F, sb+L_W1, bRel);
      #pragma unroll
      for (int im=0; im<2; im++){
        int row = rowbase + im*16;
        #pragma unroll
        for (int in=0; in<4; in++){
          float* A4 = acc[in][im];
          SHFL_GATES(A4);
          int n = nbase + in*2;
          gi += bias4[in].x; gf += bias4[in].y;
          gg += bias4[in].z; go_ += bias4[in].w;
          int idx = im*4 + in;
          float cc = sigm(gf)*c1r[idx] + sigm(gi)*tanha(gg);
          c1r[idx] = cc;
          float hv = sigm(go_)*tanha(cc);
          int rl = row - rt*128;
          int nl = n - ct*32;
          *(__half*)(stage1 + rl*TROW + nl*2) = __float2half_rn(hv);
          if (r==64){
            long off = (long)row*128 + n;
            g_hT[1][off] = hv;
            g_cT[1][off] = cc;
          }
        }
      }
    }
    CLUSTER_BAR();
    if (r < 64){
      int i = tid;               // 512 uint4 over 512 threads
      int rowi = i>>2, seg = i&3;
      uint4 v = *(const uint4*)(stage0 + rowi*TROW + seg*16);
      uint32_t off = (uint32_t)rowi*SROW + (uint32_t)ct*64 + (uint32_t)seg*16;
      #pragma unroll
      for (int q=0;q<4;q++) STC16(pA0[q]+off, v);
    }
    if (r > 0 && r < 64){
      int i = tid;
      int rowi = i>>2, seg = i&3;
      uint4 v = *(const uint4*)(stage1 + rowi*TROW + seg*16);
      uint32_t off = (uint32_t)rowi*SROW + (uint32_t)ct*64 + (uint32_t)seg*16;
      #pragma unroll
      for (int q=0;q<4;q++) STC16(pA1[q]+off, v);
    }
    CLUSTER_BAR();
  }
}

// ---------------- EnKF tail ----------------
__global__ __launch_bounds__(256) void k_up(const float* __restrict__ nh, const float* __restrict__ nc,
                                            const float* qp, const float* ep){
  extern __shared__ __align__(16) float V[];
  float* mu = V + 128*129;
  int lb = blockIdx.x, l = lb>>6, b = lb&63;
  int tid = threadIdx.x;
  float q = fabsf(*qp), e = fabsf(*ep);
  for (int i=tid; i<16384; i+=256){
    int N = i>>7, n = i&127;
    float v;
    if (N < 64)
      v = g_hT[l][(N*64+b)*128 + n] + q * nh[((N*LSn + l)*BSn + b)*128 + n];
    else {
      int j2 = N - 64;
      v = g_cT[l][(j2*64+b)*128 + n] + e * nc[((j2*LSn + l)*BSn + b)*128 + n];
    }
    V[n*129 + N] = v;
  }
  __syncthreads();
  if (tid < 128){
    float sm = 0.f;
    #pragma unroll 4
    for (int N=0;N<128;N++) sm += V[tid*129 + N];
    mu[tid] = sm*(1.f/128.f);
  }
  __syncthreads();
  for (int i=tid; i<16384; i+=256){
    int n = i>>7, N = i&127;
    float v = V[n*129 + N];
    long o = ((long)(lb*128+n))*128 + N;
    g_up[o] = v;
    float am = v - mu[n];
    __nv_bfloat16 h = __float2bfloat16(am);
    g_Amh[o] = h;
    g_Aml[o] = __float2bfloat16(am - __bfloat162float(h));
  }
}

__global__ void k_hxi(const float* __restrict__ Hm, const float* __restrict__ y){
  int b = blockIdx.x, N = threadIdx.x;
  __shared__ float Hs[128];
  Hs[N] = Hm[N]; __syncthreads();
  float sm = 0.f;
  for (int n=0;n<128;n++) sm += g_up[((long)(b*128+n))*128 + N] * Hs[n];
  __shared__ float red[128];
  red[N] = sm; __syncthreads();
  for (int st=64;st>0;st>>=1){ if (N<st) red[N]+=red[N+st]; __syncthreads(); }
  float mean = red[0]*(1.f/128.f);
  g_HA[b*128+N] = sm - mean;
  g_innov[b*128+N] = y[b] - sm;
}

__global__ void k_P(const float* rp){
  int c = blockIdx.x, d = threadIdx.x;
  float sm = 0.f;
  for (int N=0;N<128;N++) sm += g_HA[c*128+N]*g_HA[d*128+N];
  float r = *rp;
  g_P[c*64+d] = sm*(1.f/127.f) + (c==d ? r*r : 0.f);
}

__global__ __launch_bounds__(256) void k_inv(){
  __shared__ float M[64][129];
  __shared__ float fcol[64];
  int tid = threadIdx.x;
  for (int e=tid;e<8192;e+=256){
    int r = e>>7, c = e&127;
    M[r][c] = (c<64) ? g_P[r*64+c] : ((c-64)==r ? 1.f : 0.f);
  }
  __syncthreads();
  for (int k=0;k<64;k++){
    float rpv = 1.f / M[k][k];
    __syncthreads();
    if (tid < 128) M[k][tid] *= rpv;
    else if (tid < 192){
      int r = tid - 128;
      fcol[r] = (r==k) ? 0.f : M[r][k];
    }
    __syncthreads();
    for (int e=tid;e<8192;e+=256){
      int r = e>>7, c = e&127;
      M[r][c] = fmaf(-fcol[r], M[k][c], M[r][c]);
    }
    __syncthreads();
  }
  for (int e=tid;e<4096;e+=256){
    int r = e>>6, d = e&63;
    g_Pinv[r*64+d] = M[r][64+d];
  }
}

__global__ void k_T2(){
  int c = blockIdx.x, M = threadIdx.x;
  float sm = 0.f;
  for (int d=0;d<64;d++) sm += g_Pinv[c*64+d]*g_innov[d*128+M];
  g_T2[c*128+M] = sm;
}

__global__ void k_T1(){
  int N = blockIdx.x, M = threadIdx.x;
  __shared__ float HAc[64];
  if (M < 64) HAc[M] = g_HA[M*128 + N];
  __syncthreads();
  float sm = 0.f;
  for (int c=0;c<64;c++) sm += HAc[c]*g_T2[c*128+M];
  g_T1[N*128+M] = sm;
  __nv_bfloat16 h = __float2bfloat16(sm);
  g_T1th[M*128+N] = h;
  g_T1tl[M*128+N] = __float2bfloat16(sm - __bfloat162float(h));
}

// ---------------- HMMA k_upd ----------------
__global__ __launch_bounds__(256,1) void k_upd(float* __restrict__ out){
  extern __shared__ __align__(16) char smem[];
  MMA_GEO();
  LDSM_GEO();
  (void)g; (void)csel; (void)s;
  uint32_t sb = s2u(smem);
  int lb = blockIdx.x;
  cp_tile(&g_Amh[(long)lb*16384], smem+X_AH, tid);
  cp_tile(&g_Aml[(long)lb*16384], smem+X_AL, tid);
  cp_tile(&g_T1th[0], smem+X_W0, tid);
  cp_tile(&g_T1tl[0], smem+X_W1, tid);
  __syncthreads();
  float acc[8][2][4];
  #pragma unroll
  for (int in=0;in<8;in++)
    #pragma unroll
    for (int im=0;im<2;im++)
      #pragma unroll
      for (int r=0;r<4;r++) acc[in][im][r] = 0.f;
  gemm_phase(acc, sb+X_AH+aRel, sb+X_AL+aRel, sb+X_W0, sb+X_W1, bRel);

  int r2 = lane>>2, cb2 = (lane&3)*2;
  #pragma unroll
  for (int im=0; im<2; im++){
    #pragma unroll
    for (int in=0; in<8; in++){
      float* A4 = acc[in][im];
      int row0 = wm*32 + im*16 + r2;
      int col  = wn*64 + in*8 + cb2;
      long i0 = (long)lb*16384 + (long)row0*128 + col;
      long i1 = i0 + 8*128;
      float2 u0 = *(const float2*)&g_up[i0];
      float2 u1 = *(const float2*)&g_up[i1];
      float2 o0, o1;
      o0.x = u0.x + A4[0]*(1.f/127.f); o0.y = u0.y + A4[1]*(1.f/127.f);
      o1.x = u1.x + A4[2]*(1.f/127.f); o1.y = u1.y + A4[3]*(1.f/127.f);
      *(float2*)&out[OUT_X + i0] = o0;
      *(float2*)&out[OUT_X + i1] = o1;
    }
  }
}

// ---------------- HMMA k_cov ----------------
#define CV_SF 0
#define CV_T0 67584
#define CV_T1 102400
#define SMEM_CV 137216
__global__ __launch_bounds__(256,1) void k_cov(float* __restrict__ out){
  extern __shared__ __align__(16) char smem[];
  float* Sf = (float*)(smem + CV_SF);
  __shared__ float mu[128];
  __shared__ float part[256];
  MMA_GEO();
  LDSM_GEO();
  (void)g; (void)csel; (void)s;
  uint32_t sb = s2u(smem);
  int lb = blockIdx.x;
  const float* Xb = out + OUT_X + (long)lb*16384;
  for (int i=tid; i<16384; i+=256){
    int n = i>>7, k = i&127;
    Sf[k*132 + n] = Xb[i];
  }
  __syncthreads();
  {
    int n = tid & 127, half = tid >> 7;
    float sm = 0.f;
    for (int k=half*64; k<half*64+64; k++) sm += Sf[k*132 + n];
    part[tid] = sm;
    __syncthreads();
    if (tid < 128) mu[tid] = (part[tid] + part[tid+128])*(1.f/128.f);
    __syncthreads();
  }
  for (int i=tid; i<16384; i+=256){
    int n = i>>7, k = i&127;
    float a = Sf[k*132 + n] - mu[n];
    __nv_bfloat16 h = __float2bfloat16(a);
    *(__nv_bfloat16*)(smem + CV_T0 + n*SROW + k*2) = h;
    *(__nv_bfloat16*)(smem + CV_T1 + n*SROW + k*2) = __float2bfloat16(a - __bfloat162float(h));
  }
  __syncthreads();
  float acc[8][2][4];
  #pragma unroll
  for (int in=0;in<8;in++)
    #pragma unroll
    for (int im=0;im<2;im++)
      #pragma unroll
      for (int r=0;r<4;r++) acc[in][im][r] = 0.f;
  gemm_phase(acc, sb+CV_T0+aRel, sb+CV_T1+aRel, sb+CV_T0, sb+CV_T1, bRel);

  int r2 = lane>>2, cb2 = (lane&3)*2;
  #pragma unroll
  for (int im=0; im<2; im++){
    #pragma unroll
    for (int in=0; in<8; in++){
      float* A4 = acc[in][im];
      int row0 = wm*32 + im*16 + r2;
      int col  = wn*64 + in*8 + cb2;
      long i0 = OUT_COV + (long)lb*16384 + (long)row0*128 + col;
      long i1 = i0 + 8*128;
      float2 o0, o1;
      o0.x = A4[0]*(1.f/127.f); o0.y = A4[1]*(1.f/127.f);
      o1.x = A4[2]*(1.f/127.f); o1.y = A4[3]*(1.f/127.f);
      *(float2*)&out[i0] = o0;
      *(float2*)&out[i1] = o1;
    }
  }
}

__global__ void k_Y(const float* __restrict__ Hm, float* __restrict__ out){
  int b = blockIdx.x, N = threadIdx.x;
  __shared__ float Hs[128];
  Hs[N] = Hm[N]; __syncthreads();
  float sm = 0.f;
  for (int n=0;n<128;n++) sm += out[OUT_X + (long)b*16384 + n*128 + N] * Hs[n];
  __shared__ float red[128];
  red[N] = sm; __syncthreads();
  for (int st=64;st>0;st>>=1){ if (N<st) red[N]+=red[N+st]; __syncthreads(); }
  float mean = red[0]*(1.f/128.f);
  g_AY[b*128+N] = sm - mean;
  if (N==0){ g_fout[b] = mean; out[OUT_FO + b] = mean; }
}

__global__ void k_fcov(const float* rp, float* __restrict__ out){
  int c = blockIdx.x, d = threadIdx.x;
  float sm = 0.f;
  for (int N=0;N<128;N++) sm += g_AY[c*128+N]*g_AY[d*128+N];
  float r = *rp;
  float v = sm*(1.f/127.f) + (c==d ? r*r : 0.f);
  g_fcov[c*64+d] = v;
  out[OUT_FCOV + c*64+d] = v;
}

__global__ void k_ll(const float* __restrict__ y, float* __restrict__ out){
  __shared__ float A[64][65];
  __shared__ float red[64];
  int tid = threadIdx.x;
  for (int c=0;c<64;c++) A[tid][c] = g_fcov[tid*64+c];
  __syncthreads();
  for (int k=0;k<64;k++){
    if (tid==k) A[k][k] = sqrtf(A[k][k]);
    __syncthreads();
    float lkk = A[k][k];
    if (tid>k) A[tid][k] /= lkk;
    __syncthreads();
    if (tid>k){
      float lrk = A[tid][k];
      for (int c=k+1;c<=tid;c++) A[tid][c] -= lrk*A[c][k];
    }
    __syncthreads();
  }
  red[tid] = 2.f*logf(A[tid][tid]);
  __syncthreads();
  for (int st=32;st>0;st>>=1){ if (tid<st) red[tid]+=red[tid+st]; __syncthreads(); }
  if (tid==0){
    float logdet = red[0];
    float z[64];
    for (int k=0;k<64;k++){
      float sm = y[k] - g_fout[k];
      for (int j=0;j<k;j++) sm -= A[k][j]*z[j];
      z[k] = sm / A[k][k];
    }
    float qs = 0.f;
    for (int k=0;k<64;k++) qs += z[k]*z[k];
    out[OUT_LL] = -0.5f*logdet - 0.5f*qs;
  }
}

extern "C" void kernel_launch(void* const* d_in, const int* in_sizes, int n_in,
                              void* d_out, int out_size){
  const float* x    = (const float*)d_in[0];
  const float* y    = (const float*)d_in[1];
  const float* uhi  = (const float*)d_in[2];
  const float* W_ih = (const float*)d_in[3];
  const float* W_hh = (const float*)d_in[4];
  const float* b_ih = (const float*)d_in[5];
  const float* b_hh = (const float*)d_in[6];
  const float* Hm   = (const float*)d_in[7];
  const float* q    = (const float*)d_in[8];
  const float* e    = (const float*)d_in[9];
  const float* r    = (const float*)d_in[10];
  const float* nh   = (const float*)d_in[11];
  const float* nc   = (const float*)d_in[12];
  float* out = (float*)d_out;

  static int smem_set = 0;
  if (!smem_set){
    cudaFuncSetAttribute(k_lstm,   cudaFuncAttributeMaxDynamicSharedMemorySize, SMEM_L);
    cudaFuncSetAttribute(k_xprojM, cudaFuncAttributeMaxDynamicSharedMemorySize, SMEM_X);
    cudaFuncSetAttribute(k_upd,    cudaFuncAttributeMaxDynamicSharedMemorySize, SMEM_X);
    cudaFuncSetAttribute(k_cov,    cudaFuncAttributeMaxDynamicSharedMemorySize, SMEM_CV);
    cudaFuncSetAttribute(k_init,   cudaFuncAttributeMaxDynamicSharedMemorySize, 128*129*4);
    cudaFuncSetAttribute(k_up,     cudaFuncAttributeMaxDynamicSharedMemorySize, 128*129*4 + 512);
    smem_set = 1;
  }

  k_init<<<128, 256, 128*129*4>>>(uhi);                 // 0
  k_prep<<<2820, 256>>>(W_ih, W_hh, x, b_ih, b_hh);     // 1
  k_xprojM<<<128, 256, SMEM_X>>>();                     // 2
  k_lstm<<<128, 512, SMEM_L>>>();                       // 3 <- profiled

  k_up<<<128, 256, 128*129*4 + 512>>>(nh, nc, q, e);
  k_hxi<<<64, 128>>>(Hm, y);
  k_P<<<64, 64>>>(r);
  k_inv<<<1, 256>>>();
  k_T2<<<64, 128>>>();
  k_T1<<<128, 128>>>();
  k_upd<<<128, 256, SMEM_X>>>(out);
  k_cov<<<128, 256, SMEM_CV>>>(out);
  k_Y<<<64, 128>>>(Hm, out);
  k_fcov<<<64, 64>>>(r, out);
  k_ll<<<1, 64>>>(y, out);
}

// round 16
// speedup vs baseline: 1.1652x; 1.0008x over previous
#include <cuda_runtime.h>
#include <cuda_bf16.h>
#include <cuda_fp16.h>
#include <cstdint>
#include <math.h>

#define LSn 2
#define BSn 64
#define Tn 64
#define NHn 128
#define HW (4096*128)
#define OUT_FO   0
#define OUT_FCOV 64
#define OUT_X    4160
#define OUT_COV  2101312
#define OUT_LL   4198464

// ---------------- device scratch ----------------
__device__ __align__(256) __half g_h0i[HW];
__device__ __align__(256) __half g_h1i[HW];
__device__ __align__(256) __half g_Whh[2][512*128];
__device__ __align__(256) __half g_Wih[512*128];
__device__ __align__(256) __nv_bfloat16 g_Wi0hi[512*128];
__device__ __align__(256) __nv_bfloat16 g_Wi0lo[512*128];
__device__ __align__(256) __nv_bfloat16 g_xhi[4096*128];
__device__ __align__(256) __nv_bfloat16 g_xlo[4096*128];
__device__ float g_c0[2][HW];
__device__ float g_hT[2][HW];
__device__ float g_cT[2][HW];
__device__ __align__(256) float g_xproj[Tn*64*128*4];
__device__ __align__(16) float g_bsum2[512];
__device__ __align__(16) float g_bsum0v[512];

__device__ float g_up[2*64*128*128];
__device__ __align__(256) __nv_bfloat16 g_Amh[2*64*128*128];
__device__ __align__(256) __nv_bfloat16 g_Aml[2*64*128*128];
__device__ float g_HA[64*128];
__device__ float g_innov[64*128];
__device__ float g_P[64*64];
__device__ float g_Pinv[64*64];
__device__ float g_T2[64*128];
__device__ float g_T1[128*128];
__device__ __align__(256) __nv_bfloat16 g_T1th[128*128];
__device__ __align__(256) __nv_bfloat16 g_T1tl[128*128];
__device__ float g_AY[64*128];
__device__ float g_fout[64];
__device__ float g_fcov[64*64];

__device__ __forceinline__ float tanha(float x){
  float r; asm("tanh.approx.f32 %0, %1;" : "=f"(r) : "f"(x)); return r;
}
__device__ __forceinline__ float sigm(float x){ return fmaf(0.5f, tanha(0.5f*x), 0.5f); }
__device__ __forceinline__ uint32_t s2u(const void* p){
  uint32_t a;
  asm("{ .reg .u64 t; cvta.to.shared.u64 t, %1; cvt.u32.u64 %0, t; }" : "=r"(a) : "l"(p));
  return a;
}

#define SROW 272
#define TROW 80

#define MMA_BF16(d, a, b0_, b1_) \
  asm volatile("mma.sync.aligned.m16n8k16.row.col.f32.bf16.bf16.f32 " \
    "{%0,%1,%2,%3},{%4,%5,%6,%7},{%8,%9},{%0,%1,%2,%3};" \
    : "+f"((d)[0]),"+f"((d)[1]),"+f"((d)[2]),"+f"((d)[3]) \
    : "r"((a)[0]),"r"((a)[1]),"r"((a)[2]),"r"((a)[3]),"r"(b0_),"r"(b1_))

#define MMA_F16(d, a, b0_, b1_) \
  asm volatile("mma.sync.aligned.m16n8k16.row.col.f32.f16.f16.f32 " \
    "{%0,%1,%2,%3},{%4,%5,%6,%7},{%8,%9},{%0,%1,%2,%3};" \
    : "+f"((d)[0]),"+f"((d)[1]),"+f"((d)[2]),"+f"((d)[3]) \
    : "r"((a)[0]),"r"((a)[1]),"r"((a)[2]),"r"((a)[3]),"r"(b0_),"r"(b1_))

#define LDSM4(r, a) \
  asm volatile("ldmatrix.sync.aligned.m8n8.x4.shared.b16 {%0,%1,%2,%3}, [%4];" \
    : "=r"((r)[0]),"=r"((r)[1]),"=r"((r)[2]),"=r"((r)[3]) : "r"(a))

#define CLUSTER_BAR() do{ \
  asm volatile("barrier.cluster.arrive.aligned;" ::: "memory"); \
  asm volatile("barrier.cluster.wait.aligned;" ::: "memory"); }while(0)

#define CPA16(dst, src) \
  asm volatile("cp.async.ca.shared.global [%0], [%1], 16;" :: "r"(dst), "l"(src))
#define CPA_COMMIT() asm volatile("cp.async.commit_group;" ::: "memory")
#define CPA_WAIT0()  asm volatile("cp.async.wait_group 0;" ::: "memory")

#define STC16(addr, v) \
  asm volatile("st.shared::cluster.v4.b32 [%0], {%1,%2,%3,%4};" \
    :: "r"(addr), "r"((v).x), "r"((v).y), "r"((v).z), "r"((v).w) : "memory")

__device__ __forceinline__ void cp_tile(const __nv_bfloat16* __restrict__ src, char* dst, int tid){
  const uint4* s4 = (const uint4*)src;
  #pragma unroll
  for (int it=0; it<8; it++){
    int i = it*256 + tid;
    uint4 v = __ldcg(&s4[i]);
    int row = i>>4, ck = i&15;
    *(uint4*)(dst + row*SROW + ck*16) = v;
  }
}

__device__ __forceinline__ void cp_tile_a512(const void* __restrict__ src, uint32_t dst, int tid){
  const uint4* s4 = (const uint4*)src;
  #pragma unroll
  for (int it=0; it<4; it++){
    int i = it*512 + tid;
    int row = i>>4, ck = i&15;
    CPA16(dst + row*SROW + ck*16, &s4[i]);
  }
}

// 3-term bf16-split GEMM (tail kernels, 256 threads)
__device__ __forceinline__ void gemm_phase(float acc[8][2][4],
                                           uint32_t aH, uint32_t aL,
                                           uint32_t bH, uint32_t bL,
                                           const uint32_t* bRel){
  #pragma unroll
  for (int kc=0; kc<8; kc++){
    uint32_t ka = kc*32;
    uint32_t ah0[4], ah1[4], al0[4], al1[4];
    LDSM4(ah0, aH + ka);
    LDSM4(ah1, aH + 16*SROW + ka);
    LDSM4(al0, aL + ka);
    LDSM4(al1, aL + 16*SROW + ka);
    #pragma unroll
    for (int jp2=0; jp2<2; jp2++){
      uint32_t bh0[4], bh1[4], bl0[4], bl1[4];
      LDSM4(bh0, bH + bRel[jp2*2]   + ka);
      LDSM4(bh1, bH + bRel[jp2*2+1] + ka);
      LDSM4(bl0, bL + bRel[jp2*2]   + ka);
      LDSM4(bl1, bL + bRel[jp2*2+1] + ka);
      int p0 = jp2*4, p1 = p0+1, p2 = p0+2, p3 = p0+3;
      MMA_BF16(acc[p0][0], ah0, bh0[0], bh0[1]);
      MMA_BF16(acc[p0][1], ah1, bh0[0], bh0[1]);
      MMA_BF16(acc[p1][0], ah0, bh0[2], bh0[3]);
      MMA_BF16(acc[p1][1], ah1, bh0[2], bh0[3]);
      MMA_BF16(acc[p2][0], ah0, bh1[0], bh1[1]);
      MMA_BF16(acc[p2][1], ah1, bh1[0], bh1[1]);
      MMA_BF16(acc[p3][0], ah0, bh1[2], bh1[3]);
      MMA_BF16(acc[p3][1], ah1, bh1[2], bh1[3]);
      MMA_BF16(acc[p0][0], ah0, bl0[0], bl0[1]);
      MMA_BF16(acc[p0][1], ah1, bl0[0], bl0[1]);
      MMA_BF16(acc[p1][0], ah0, bl0[2], bl0[3]);
      MMA_BF16(acc[p1][1], ah1, bl0[2], bl0[3]);
      MMA_BF16(acc[p2][0], ah0, bl1[0], bl1[1]);
      MMA_BF16(acc[p2][1], ah1, bl1[0], bl1[1]);
      MMA_BF16(acc[p3][0], ah0, bl1[2], bl1[3]);
      MMA_BF16(acc[p3][1], ah1, bl1[2], bl1[3]);
      MMA_BF16(acc[p0][0], al0, bh0[0], bh0[1]);
      MMA_BF16(acc[p0][1], al1, bh0[0], bh0[1]);
      MMA_BF16(acc[p1][0], al0, bh0[2], bh0[3]);
      MMA_BF16(acc[p1][1], al1, bh0[2], bh0[3]);
      MMA_BF16(acc[p2][0], al0, bh1[0], bh1[1]);
      MMA_BF16(acc[p2][1], al1, bh1[0], bh1[1]);
      MMA_BF16(acc[p3][0], al0, bh1[2], bh1[3]);
      MMA_BF16(acc[p3][1], al1, bh1[2], bh1[3]);
    }
  }
}

// 1-term fp16 GEMM, 32x32 warp tile, 16 warps
__device__ __forceinline__ void gemm_phase1h(float acc[4][2][4],
                                             uint32_t aF, uint32_t bF,
                                             const uint32_t* bRel){
  #pragma unroll
  for (int kc=0; kc<8; kc++){
    uint32_t ka = kc*32;
    uint32_t a0[4], a1[4], b0[4], b1[4];
    LDSM4(a0, aF + ka);
    LDSM4(a1, aF + 16*SROW + ka);
    LDSM4(b0, bF + bRel[0] + ka);
    LDSM4(b1, bF + bRel[1] + ka);
    MMA_F16(acc[0][0], a0, b0[0], b0[1]);
    MMA_F16(acc[0][1], a1, b0[0], b0[1]);
    MMA_F16(acc[1][0], a0, b0[2], b0[3]);
    MMA_F16(acc[1][1], a1, b0[2], b0[3]);
    MMA_F16(acc[2][0], a0, b1[0], b1[1]);
    MMA_F16(acc[2][1], a1, b1[0], b1[1]);
    MMA_F16(acc[3][0], a0, b1[2], b1[3]);
    MMA_F16(acc[3][1], a1, b1[2], b1[3]);
  }
}

#define MMA_GEO() \
  int tid = threadIdx.x, wid = tid>>5, lane = tid&31; \
  int g = lane>>2; \
  int wm = wid&3, wn = wid>>2; \
  int s = (lane&3)&1, csel = (lane&3)>>1; \
  int src_if = (g<<2) + (csel<<1); \
  int src_go = src_if + 1; (void)src_if; (void)src_go;

#define LDSM_GEO() \
  int aq = lane>>3, ar = lane&7; \
  uint32_t aRel = (uint32_t)(wm*32 + (aq&1)*8 + ar)*SROW + (uint32_t)(aq>>1)*16; \
  uint32_t bRel[4]; \
  { int bq = lane>>3, br = lane&7; \
    _Pragma("unroll") \
    for (int jp=0; jp<4; jp++) \
      bRel[jp] = (uint32_t)(wn*64 + (jp*2 + (bq>>1))*8 + br)*SROW + (uint32_t)(bq&1)*16; }

#define SHFL_GATES(A4) \
  float v0 = __shfl_sync(0xFFFFFFFFu, A4[0], src_if); \
  float v2 = __shfl_sync(0xFFFFFFFFu, A4[2], src_if); \
  float v1 = __shfl_sync(0xFFFFFFFFu, A4[1], src_if); \
  float v3 = __shfl_sync(0xFFFFFFFFu, A4[3], src_if); \
  float w0 = __shfl_sync(0xFFFFFFFFu, A4[0], src_go); \
  float w2 = __shfl_sync(0xFFFFFFFFu, A4[2], src_go); \
  float w1 = __shfl_sync(0xFFFFFFFFu, A4[1], src_go); \
  float w3 = __shfl_sync(0xFFFFFFFFu, A4[3], src_go); \
  float gi  = s ? v2 : v0; \
  float gf  = s ? v3 : v1; \
  float gg  = s ? w2 : w0; \
  float go_ = s ? w3 : w1;

// ---------------- prep ----------------
__global__ __launch_bounds__(256) void k_init(const float* __restrict__ uhi){
  extern __shared__ __align__(16) float U[];
  int lb = blockIdx.x, l = lb>>6, b = lb&63;
  int tid = threadIdx.x;
  const float* src = uhi + (long)lb*16384;
  for (int i=tid;i<16384;i+=256) U[(i>>7)*129 + (i&127)] = src[i];
  __syncthreads();
  for (int i=tid;i<8192;i+=256){
    int j = i>>7, k = i&127;
    int row = (j*64+b)*128 + k;
    __half hv = __float2half_rn(U[k*129 + j]);
    if (l==0) g_h0i[row] = hv; else g_h1i[row] = hv;
    g_c0[l][row] = U[k*129 + j + 64];
  }
}

__global__ void k_prep(const float* __restrict__ W_ih, const float* __restrict__ W_hh,
                       const float* __restrict__ x,
                       const float* __restrict__ bih, const float* __restrict__ bhh){
  int idx = blockIdx.x*blockDim.x + threadIdx.x;
  if (idx < 131072){
    int k = idx & 127, cg = (idx>>7)&511, l = idx>>16;
    int ct = cg>>7, c = cg&127;
    int nat = (c&3)*128 + ct*32 + (c>>2);
    g_Whh[l][cg*128+k] = __float2half_rn(W_hh[l*65536 + nat*128 + k]);
    if (l==1)
      g_Wih[cg*128+k] = __float2half_rn(W_ih[65536 + nat*128 + k]);
  } else if (idx < 196608){
    int i2 = idx - 131072;
    int k = i2 & 127, cg = i2>>7;
    int ct = cg>>7, c = cg&127;
    int nat = (c&3)*128 + ct*32 + (c>>2);
    float wi = W_ih[nat*128 + k];
    __nv_bfloat16 ihi = __float2bfloat16(wi);
    g_Wi0hi[cg*128+k] = ihi;
    g_Wi0lo[cg*128+k] = __float2bfloat16(wi - __bfloat162float(ihi));
  } else if (idx < 720896){
    int i2 = idx - 196608;
    int d = i2 & 127, row = i2 >> 7;
    int b = row & 63, t = row >> 6;
    float v = x[(b*Tn + t)*128 + d];
    __nv_bfloat16 hi = __float2bfloat16(v);
    g_xhi[row*128+d] = hi;
    g_xlo[row*128+d] = __float2bfloat16(v - __bfloat162float(hi));
  } else {
    int i2 = idx - 720896;
    if (i2 < 1024){
      int ll = i2>>9, c = i2&511;
      float v = bih[i2] + bhh[i2];
      if (ll==1) g_bsum2[(c&127)*4 + (c>>7)] = v;
      else       g_bsum0v[(c&127)*4 + (c>>7)] = v;
    }
  }
}

#define X_AH 0
#define X_AL 34816
#define X_W0 69632
#define X_W1 104448
#define SMEM_X 139264
#define L_A0 0
#define L_A1 34816
#define L_W0 69632
#define L_W1 104448
#define L_W2 139264
#define L_ST 174080
#define L_XP 194560
#define SMEM_L (194560 + 33792)

// ---------------- HMMA xproj (bf16, 3-term, exact) ----------------
__global__ __launch_bounds__(256,1) void k_xprojM(){
  extern __shared__ __align__(16) char smem[];
  MMA_GEO();
  LDSM_GEO();
  uint32_t sb = s2u(smem);
  int rt = blockIdx.x>>2, ct = blockIdx.x&3;
  int rowbase = rt*128 + wm*32 + g + 8*s;
  int nbase   = ct*32 + wn*16 + csel;
  float4 bias4[8];
  #pragma unroll
  for (int in=0; in<8; in++) bias4[in] = ((const float4*)g_bsum0v)[nbase + in*2];

  cp_tile(&g_xhi[rt*16384], smem+X_AH, tid);
  cp_tile(&g_xlo[rt*16384], smem+X_AL, tid);
  cp_tile(&g_Wi0hi[ct*16384], smem+X_W0, tid);
  cp_tile(&g_Wi0lo[ct*16384], smem+X_W1, tid);
  __syncthreads();
  float acc[8][2][4];
  #pragma unroll
  for (int in=0;in<8;in++)
    #pragma unroll
    for (int im=0;im<2;im++)
      #pragma unroll
      for (int r=0;r<4;r++) acc[in][im][r] = 0.f;
  gemm_phase(acc, sb+X_AH+aRel, sb+X_AL+aRel, sb+X_W0, sb+X_W1, bRel);

  float4* dst = (float4*)g_xproj;
  #pragma unroll
  for (int im=0; im<2; im++){
    int row = rowbase + im*16;
    #pragma unroll
    for (int in=0; in<8; in++){
      float* A4 = acc[in][im];
      SHFL_GATES(A4);
      int n = nbase + in*2;
      float4 v;
      v.x = gi + bias4[in].x; v.y = gf + bias4[in].y;
      v.z = gg + bias4[in].z; v.w = go_ + bias4[in].w;
      __stcg(&dst[(long)row*128 + n], v);
    }
  }
}

// ---------------- persistent wavefront 2-layer fp16 LSTM (512 thr, xproj smem prefetch) ----------------
__global__ __launch_bounds__(512,1) __cluster_dims__(4,1,1) void k_lstm(){
  extern __shared__ __align__(16) char smem[];
  char* stage0 = smem + L_ST;
  char* stage1 = smem + L_ST + 10240;
  int tid = threadIdx.x, wid = tid>>5, lane = tid&31;
  int g = lane>>2;
  int wm = wid&3, wn = wid>>2;
  int s = lane&1, csel = (lane&3)>>1;
  int src_if = (g<<2) + (csel<<1);
  int src_go = src_if + 1;
  int aq = lane>>3, ar = lane&7;
  uint32_t aRel = (uint32_t)(wm*32 + (aq&1)*8 + ar)*SROW + (uint32_t)(aq>>1)*16;
  uint32_t bRel[2];
  { int bq = lane>>3, br = lane&7;
    #pragma unroll
    for (int jp=0; jp<2; jp++)
      bRel[jp] = (uint32_t)(wn*32 + (jp*2 + (bq>>1))*8 + br)*SROW + (uint32_t)(bq&1)*16; }
  uint32_t sb = s2u(smem);
  uint32_t a0F = sb + L_A0 + aRel, a1F = sb + L_A1 + aRel;
  int rt = blockIdx.x>>2, ct = blockIdx.x&3;
  int rowbase = rt*128 + wm*32 + g + 8*s;
  int nbase   = ct*32 + wn*8 + csel;
  float c0r[8], c1r[8];
  float4 bias4[4];

  uint32_t pA0[4], pA1[4];
  #pragma unroll
  for (int p=0;p<4;p++){
    asm("mapa.shared::cluster.u32 %0, %1, %2;" : "=r"(pA0[p]) : "r"(sb+L_A0), "r"(p));
    asm("mapa.shared::cluster.u32 %0, %1, %2;" : "=r"(pA1[p]) : "r"(sb+L_A1), "r"(p));
  }

  cp_tile_a512(&g_h0i[rt*16384], sb+L_A0, tid);
  cp_tile_a512(&g_h1i[rt*16384], sb+L_A1, tid);
  cp_tile_a512(&g_Whh[0][ct*16384], sb+L_W0, tid);
  cp_tile_a512(&g_Whh[1][ct*16384], sb+L_W1, tid);
  cp_tile_a512(&g_Wih[ct*16384],    sb+L_W2, tid);
  #pragma unroll
  for (int in=0; in<4; in++) bias4[in] = ((const float4*)g_bsum2)[nbase + in*2];
  #pragma unroll
  for (int im=0; im<2; im++)
    #pragma unroll
    for (int in=0; in<4; in++){
      c0r[im*4+in] = g_c0[0][(long)(rowbase+im*16)*128 + nbase + in*2];
      c1r[im*4+in] = g_c0[1][(long)(rowbase+im*16)*128 + nbase + in*2];
    }
  CPA_COMMIT(); CPA_WAIT0();
  CLUSTER_BAR();

  const float4* xs = (const float4*)(smem + L_XP);
  for (int r=0; r<65; r++){
    float acc[4][2][4];
    if (r < 64){
      // prefetch this round's xproj slice: [b 0..63][nl 0..31] float4, pad 33
      #pragma unroll
      for (int it=0; it<4; it++){
        int i = it*512 + tid;
        int b = i>>5, nl = i&31;
        const char* src = (const char*)g_xproj +
          ((((long)r*64 + b)*128) + ct*32 + nl)*16;
        CPA16(sb + L_XP + (uint32_t)(b*33 + nl)*16, src);
      }
      CPA_COMMIT();
      #pragma unroll
      for (int in=0;in<4;in++)
        #pragma unroll
        for (int im=0;im<2;im++)
          #pragma unroll
          for (int q=0;q<4;q++) acc[in][im][q] = 0.f;
      gemm_phase1h(acc, a0F, sb+L_W0, bRel);
      CPA_WAIT0();
      #pragma unroll
      for (int im=0; im<2; im++){
        int row = rowbase + im*16;
        int b33 = (row & 63)*33;
        #pragma unroll
        for (int in=0; in<4; in++){
          float* A4 = acc[in][im];
          SHFL_GATES(A4);
          int n = nbase + in*2;
          int nl = n - ct*32;
          float4 xg = xs[b33 + nl];
          gi += xg.x; gf += xg.y; gg += xg.z; go_ += xg.w;
          int idx = im*4 + in;
          float cc = sigm(gf)*c0r[idx] + sigm(gi)*tanha(gg);
          c0r[idx] = cc;
          float hv = sigm(go_)*tanha(cc);
          int rl = row - rt*128;
          *(__half*)(stage0 + rl*TROW + nl*2) = __float2half_rn(hv);
          if (r==63){
            long off = (long)row*128 + n;
            g_hT[0][off] = hv;
            g_cT[0][off] = cc;
          }
        }
      }
    }
    if (r > 0){
      #pragma unroll
      for (int in=0;in<4;in++)
        #pragma unroll
        for (int im=0;im<2;im++)
          #pragma unroll
          for (int q=0;q<4;q++) acc[in][im][q] = 0.f;
      gemm_phase1h(acc, a0F, sb+L_W2, bRel);
      gemm_phase1h(acc, a1F, sb+L_W1, bRel);
      #pragma unroll
      for (int im=0; im<2; im++){
        int row = rowbase + im*16;
        #pragma unroll
        for (int in=0; in<4; in++){
          float* A4 = acc[in][im];
          SHFL_GATES(A4);
          int n = nbase + in*2;
          gi += bias4[in].x; gf += bias4[in].y;
          gg += bias4[in].z; go_ += bias4[in].w;
          int idx = im*4 + in;
          float cc = sigm(gf)*c1r[idx] + sigm(gi)*tanha(gg);
          c1r[idx] = cc;
          float hv = sigm(go_)*tanha(cc);
          int rl = row - rt*128;
          int nl = n - ct*32;
          *(__half*)(stage1 + rl*TROW + nl*2) = __float2half_rn(hv);
          if (r==64){
            long off = (long)row*128 + n;
            g_hT[1][off] = hv;
            g_cT[1][off] = cc;
          }
        }
      }
    }
    CLUSTER_BAR();
    if (r < 64){
      int i = tid;
      int rowi = i>>2, seg = i&3;
      uint4 v = *(const uint4*)(stage0 + rowi*TROW + seg*16);
      uint32_t off = (uint32_t)rowi*SROW + (uint32_t)ct*64 + (uint32_t)seg*16;
      #pragma unroll
      for (int q=0;q<4;q++) STC16(pA0[q]+off, v);
    }
    if (r > 0 && r < 64){
      int i = tid;
      int rowi = i>>2, seg = i&3;
      uint4 v = *(const uint4*)(stage1 + rowi*TROW + seg*16);
      uint32_t off = (uint32_t)rowi*SROW + (uint32_t)ct*64 + (uint32_t)seg*16;
      #pragma unroll
      for (int q=0;q<4;q++) STC16(pA1[q]+off, v);
    }
    CLUSTER_BAR();
  }
}

// ---------------- EnKF tail ----------------
// coalesced per-(l,b) block; l=0 blocks also compute hxi/HA/innov (fused k_hxi)
__global__ __launch_bounds__(256) void k_up(const float* __restrict__ nh, const float* __restrict__ nc,
                                            const float* qp, const float* ep,
                                            const float* __restrict__ Hm, const float* __restrict__ y){
  extern __shared__ __align__(16) float V[];   // [128 n][129]
  __shared__ float mu[128];
  __shared__ float Hs[128];
  __shared__ float part[256];
  __shared__ float hx[128];
  __shared__ float red[128];
  int lb = blockIdx.x, l = lb>>6, b = lb&63;
  int tid = threadIdx.x;
  float q = fabsf(*qp), e = fabsf(*ep);
  if (tid < 128) Hs[tid] = Hm[tid];
  for (int i=tid; i<16384; i+=256){
    int N = i>>7, n = i&127;
    float v;
    if (N < 64)
      v = g_hT[l][(N*64+b)*128 + n] + q * nh[((N*LSn + l)*BSn + b)*128 + n];
    else {
      int j2 = N - 64;
      v = g_cT[l][(j2*64+b)*128 + n] + e * nc[((j2*LSn + l)*BSn + b)*128 + n];
    }
    V[n*129 + N] = v;
  }
  __syncthreads();
  if (tid < 128){
    float sm = 0.f;
    #pragma unroll 4
    for (int N=0;N<128;N++) sm += V[tid*129 + N];
    mu[tid] = sm*(1.f/128.f);
  }
  __syncthreads();
  for (int i=tid; i<16384; i+=256){
    int n = i>>7, N = i&127;
    float v = V[n*129 + N];
    long o = ((long)(lb*128+n))*128 + N;
    g_up[o] = v;
    float am = v - mu[n];
    __nv_bfloat16 h = __float2bfloat16(am);
    g_Amh[o] = h;
    g_Aml[o] = __float2bfloat16(am - __bfloat162float(h));
  }
  if (l == 0){
    int N = tid & 127, half = tid >> 7;
    float sm = 0.f;
    for (int n=half*64; n<half*64+64; n++) sm += V[n*129 + N] * Hs[n];
    part[tid] = sm;
    __syncthreads();
    if (tid < 128){
      float v = part[tid] + part[tid+128];
      hx[tid] = v;
      red[tid] = v;
    }
    __syncthreads();
    for (int st=64; st>0; st>>=1){ if (tid<st) red[tid]+=red[tid+st]; __syncthreads(); }
    float mean = red[0]*(1.f/128.f);
    if (tid < 128){
      g_HA[b*128+tid] = hx[tid] - mean;
      g_innov[b*128+tid] = y[b] - hx[tid];
    }
  }
}

__global__ void k_P(const float* rp){
  int c = blockIdx.x, d = threadIdx.x;
  float sm = 0.f;
  for (int N=0;N<128;N++) sm += g_HA[c*128+N]*g_HA[d*128+N];
  float r = *rp;
  g_P[c*64+d] = sm*(1.f/127.f) + (c==d ? r*r : 0.f);
}

__global__ __launch_bounds__(256) void k_inv(){
  __shared__ float M[64][129];
  __shared__ float fcol[64];
  int tid = threadIdx.x;
  for (int e=tid;e<8192;e+=256){
    int r = e>>7, c = e&127;
    M[r][c] = (c<64) ? g_P[r*64+c] : ((c-64)==r ? 1.f : 0.f);
  }
  __syncthreads();
  for (int k=0;k<64;k++){
    float rpv = 1.f / M[k][k];
    __syncthreads();
    if (tid < 128) M[k][tid] *= rpv;
    else if (tid < 192){
      int r = tid - 128;
      fcol[r] = (r==k) ? 0.f : M[r][k];
    }
    __syncthreads();
    for (int e=tid;e<8192;e+=256){
      int r = e>>7, c = e&127;
      M[r][c] = fmaf(-fcol[r], M[k][c], M[r][c]);
    }
    __syncthreads();
  }
  for (int e=tid;e<4096;e+=256){
    int r = e>>6, d = e&63;
    g_Pinv[r*64+d] = M[r][64+d];
  }
}

__global__ void k_T2(){
  int c = blockIdx.x, M = threadIdx.x;
  float sm = 0.f;
  for (int d=0;d<64;d++) sm += g_Pinv[c*64+d]*g_innov[d*128+M];
  g_T2[c*128+M] = sm;
}

__global__ void k_T1(){
  int N = blockIdx.x, M = threadIdx.x;
  __shared__ float HAc[64];
  if (M < 64) HAc[M] = g_HA[M*128 + N];
  __syncthreads();
  float sm = 0.f;
  for (int c=0;c<64;c++) sm += HAc[c]*g_T2[c*128+M];
  g_T1[N*128+M] = sm;
  __nv_bfloat16 h = __float2bfloat16(sm);
  g_T1th[M*128+N] = h;
  g_T1tl[M*128+N] = __float2bfloat16(sm - __bfloat162float(h));
}

// ---------------- HMMA k_upd ----------------
__global__ __launch_bounds__(256,1) void k_upd(float* __restrict__ out){
  extern __shared__ __align__(16) char smem[];
  MMA_GEO();
  LDSM_GEO();
  (void)g; (void)csel; (void)s;
  uint32_t sb = s2u(smem);
  int lb = blockIdx.x;
  cp_tile(&g_Amh[(long)lb*16384], smem+X_AH, tid);
  cp_tile(&g_Aml[(long)lb*16384], smem+X_AL, tid);
  cp_tile(&g_T1th[0], smem+X_W0, tid);
  cp_tile(&g_T1tl[0], smem+X_W1, tid);
  __syncthreads();
  float acc[8][2][4];
  #pragma unroll
  for (int in=0;in<8;in++)
    #pragma unroll
    for (int im=0;im<2;im++)
      #pragma unroll
      for (int r=0;r<4;r++) acc[in][im][r] = 0.f;
  gemm_phase(acc, sb+X_AH+aRel, sb+X_AL+aRel, sb+X_W0, sb+X_W1, bRel);

  int r2 = lane>>2, cb2 = (lane&3)*2;
  #pragma unroll
  for (int im=0; im<2; im++){
    #pragma unroll
    for (int in=0; in<8; in++){
      float* A4 = acc[in][im];
      int row0 = wm*32 + im*16 + r2;
      int col  = wn*64 + in*8 + cb2;
      long i0 = (long)lb*16384 + (long)row0*128 + col;
      long i1 = i0 + 8*128;
      float2 u0 = *(const float2*)&g_up[i0];
      float2 u1 = *(const float2*)&g_up[i1];
      float2 o0, o1;
      o0.x = u0.x + A4[0]*(1.f/127.f); o0.y = u0.y + A4[1]*(1.f/127.f);
      o1.x = u1.x + A4[2]*(1.f/127.f); o1.y = u1.y + A4[3]*(1.f/127.f);
      *(float2*)&out[OUT_X + i0] = o0;
      *(float2*)&out[OUT_X + i1] = o1;
    }
  }
}

// ---------------- HMMA k_cov ----------------
#define CV_SF 0
#define CV_T0 67584
#define CV_T1 102400
#define SMEM_CV 137216
__global__ __launch_bounds__(256,1) void k_cov(float* __restrict__ out){
  extern __shared__ __align__(16) char smem[];
  float* Sf = (float*)(smem + CV_SF);
  __shared__ float mu[128];
  __shared__ float part[256];
  MMA_GEO();
  LDSM_GEO();
  (void)g; (void)csel; (void)s;
  uint32_t sb = s2u(smem);
  int lb = blockIdx.x;
  const float* Xb = out + OUT_X + (long)lb*16384;
  for (int i=tid; i<16384; i+=256){
    int n = i>>7, k = i&127;
    Sf[k*132 + n] = Xb[i];
  }
  __syncthreads();
  {
    int n = tid & 127, half = tid >> 7;
    float sm = 0.f;
    for (int k=half*64; k<half*64+64; k++) sm += Sf[k*132 + n];
    part[tid] = sm;
    __syncthreads();
    if (tid < 128) mu[tid] = (part[tid] + part[tid+128])*(1.f/128.f);
    __syncthreads();
  }
  for (int i=tid; i<16384; i+=256){
    int n = i>>7, k = i&127;
    float a = Sf[k*132 + n] - mu[n];
    __nv_bfloat16 h = __float2bfloat16(a);
    *(__nv_bfloat16*)(smem + CV_T0 + n*SROW + k*2) = h;
    *(__nv_bfloat16*)(smem + CV_T1 + n*SROW + k*2) = __float2bfloat16(a - __bfloat162float(h));
  }
  __syncthreads();
  float acc[8][2][4];
  #pragma unroll
  for (int in=0;in<8;in++)
    #pragma unroll
    for (int im=0;im<2;im++)
      #pragma unroll
      for (int r=0;r<4;r++) acc[in][im][r] = 0.f;
  gemm_phase(acc, sb+CV_T0+aRel, sb+CV_T1+aRel, sb+CV_T0, sb+CV_T1, bRel);

  int r2 = lane>>2, cb2 = (lane&3)*2;
  #pragma unroll
  for (int im=0; im<2; im++){
    #pragma unroll
    for (int in=0; in<8; in++){
      float* A4 = acc[in][im];
      int row0 = wm*32 + im*16 + r2;
      int col  = wn*64 + in*8 + cb2;
      long i0 = OUT_COV + (long)lb*16384 + (long)row0*128 + col;
      long i1 = i0 + 8*128;
      float2 o0, o1;
      o0.x = A4[0]*(1.f/127.f); o0.y = A4[1]*(1.f/127.f);
      o1.x = A4[2]*(1.f/127.f); o1.y = A4[3]*(1.f/127.f);
      *(float2*)&out[i0] = o0;
      *(float2*)&out[i1] = o1;
    }
  }
}

__global__ void k_Y(const float* __restrict__ Hm, float* __restrict__ out){
  int b = blockIdx.x, N = threadIdx.x;
  __shared__ float Hs[128];
  Hs[N] = Hm[N]; __syncthreads();
  float sm = 0.f;
  for (int n=0;n<128;n++) sm += out[OUT_X + (long)b*16384 + n*128 + N] * Hs[n];
  __shared__ float red[128];
  red[N] = sm; __syncthreads();
  for (int st=64;st>0;st>>=1){ if (N<st) red[N]+=red[N+st]; __syncthreads(); }
  float mean = red[0]*(1.f/128.f);
  g_AY[b*128+N] = sm - mean;
  if (N==0){ g_fout[b] = mean; out[OUT_FO + b] = mean; }
}

__global__ void k_fcov(const float* rp, float* __restrict__ out){
  int c = blockIdx.x, d = threadIdx.x;
  float sm = 0.f;
  for (int N=0;N<128;N++) sm += g_AY[c*128+N]*g_AY[d*128+N];
  float r = *rp;
  float v = sm*(1.f/127.f) + (c==d ? r*r : 0.f);
  g_fcov[c*64+d] = v;
  out[OUT_FCOV + c*64+d] = v;
}

__global__ void k_ll(const float* __restrict__ y, float* __restrict__ out){
  __shared__ float A[64][65];
  __shared__ float red[64];
  int tid = threadIdx.x;
  for (int c=0;c<64;c++) A[tid][c] = g_fcov[tid*64+c];
  __syncthreads();
  for (int k=0;k<64;k++){
    if (tid==k) A[k][k] = sqrtf(A[k][k]);
    __syncthreads();
    float lkk = A[k][k];
    if (tid>k) A[tid][k] /= lkk;
    __syncthreads();
    if (tid>k){
      float lrk = A[tid][k];
      for (int c=k+1;c<=tid;c++) A[tid][c] -= lrk*A[c][k];
    }
    __syncthreads();
  }
  red[tid] = 2.f*logf(A[tid][tid]);
  __syncthreads();
  for (int st=32;st>0;st>>=1){ if (tid<st) red[tid]+=red[tid+st]; __syncthreads(); }
  if (tid==0){
    float logdet = red[0];
    float z[64];
    for (int k=0;k<64;k++){
      float sm = y[k] - g_fout[k];
      for (int j=0;j<k;j++) sm -= A[k][j]*z[j];
      z[k] = sm / A[k][k];
    }
    float qs = 0.f;
    for (int k=0;k<64;k++) qs += z[k]*z[k];
    out[OUT_LL] = -0.5f*logdet - 0.5f*qs;
  }
}

extern "C" void kernel_launch(void* const* d_in, const int* in_sizes, int n_in,
                              void* d_out, int out_size){
  const float* x    = (const float*)d_in[0];
  const float* y    = (const float*)d_in[1];
  const float* uhi  = (const float*)d_in[2];
  const float* W_ih = (const float*)d_in[3];
  const float* W_hh = (const float*)d_in[4];
  const float* b_ih = (const float*)d_in[5];
  const float* b_hh = (const float*)d_in[6];
  const float* Hm   = (const float*)d_in[7];
  const float* q    = (const float*)d_in[8];
  const float* e    = (const float*)d_in[9];
  const float* r    = (const float*)d_in[10];
  const float* nh   = (const float*)d_in[11];
  const float* nc   = (const float*)d_in[12];
  float* out = (float*)d_out;

  static int smem_set = 0;
  if (!smem_set){
    cudaFuncSetAttribute(k_lstm,   cudaFuncAttributeMaxDynamicSharedMemorySize, SMEM_L);
    cudaFuncSetAttribute(k_xprojM, cudaFuncAttributeMaxDynamicSharedMemorySize, SMEM_X);
    cudaFuncSetAttribute(k_upd,    cudaFuncAttributeMaxDynamicSharedMemorySize, SMEM_X);
    cudaFuncSetAttribute(k_cov,    cudaFuncAttributeMaxDynamicSharedMemorySize, SMEM_CV);
    cudaFuncSetAttribute(k_init,   cudaFuncAttributeMaxDynamicSharedMemorySize, 128*129*4);
    cudaFuncSetAttribute(k_up,     cudaFuncAttributeMaxDynamicSharedMemorySize, 128*129*4);
    smem_set = 1;
  }

  k_init<<<128, 256, 128*129*4>>>(uhi);                 // 0
  k_prep<<<2820, 256>>>(W_ih, W_hh, x, b_ih, b_hh);     // 1
  k_xprojM<<<128, 256, SMEM_X>>>();                     // 2
  k_lstm<<<128, 512, SMEM_L>>>();                       // 3 <- profiled

  k_up<<<128, 256, 128*129*4>>>(nh, nc, q, e, Hm, y);
  k_P<<<64, 64>>>(r);
  k_inv<<<1, 256>>>();
  k_T2<<<64, 128>>>();
  k_T1<<<128, 128>>>();
  k_upd<<<128, 256, SMEM_X>>>(out);
  k_cov<<<128, 256, SMEM_CV>>>(out);
  k_Y<<<64, 128>>>(Hm, out);
  k_fcov<<<64, 64>>>(r, out);
  k_ll<<<1, 64>>>(y, out);
}